// round 14
// baseline (speedup 1.0000x reference)
#include <cuda_runtime.h>
#include <cuda_bf16.h>
#include <cstdint>
#include <cstddef>

// ===========================================================================
// DaConA on GB300 (sm_103 PTX target: mma.sync bf16 HMMA k16 + ldmatrix with
// hoisted swizzle addressing -- R11 winner kernels).
// R14: user/item split pipelining -- conv_u -> gemm_u starts while conv_i
// runs under it (DRAM vs tensor), then gemm_i overlaps gemm_u tail.
// Dual-stream MLP halves retained from R13.
// pred = MLP(concat(u_indep[r], i_indep[c], (Wt@u[r]+bt)*(Wt@i[c]+bt))) + 3.5
// ===========================================================================

#define NB      131072
#define NUSERS  100000
#define NITEMS  50000
#define NEMB    150000
#define DIMC    960
#define DIMS    32
#define BF_E    8
#define NBH     (NB / 2)

__device__ __nv_bfloat16 g_Eb[(size_t)NEMB * DIMC];
__device__ __nv_bfloat16 g_Wtb[(size_t)DIMC * DIMC];
__device__ __nv_bfloat16 g_T [(size_t)NEMB * DIMC];
__device__ __nv_bfloat16 g_W1b[512 * 1024];
__device__ __nv_bfloat16 g_W2b[256 * 512];
__device__ __nv_bfloat16 g_W3b[128 * 256];
__device__ __nv_bfloat16 g_F0[(size_t)NB * 1024];
__device__ __nv_bfloat16 g_F1[(size_t)NB * 512];
__device__ __nv_bfloat16 g_F2[(size_t)NB * 256];
__device__ unsigned char g_used[NEMB];
__device__ int g_list_u[NUSERS];
__device__ int g_list_i[NITEMS];
__device__ int g_cnt_u;
__device__ int g_cnt_i;

__device__ __forceinline__ uint32_t smem_u32(const void* p) {
    uint32_t a;
    asm("{ .reg .u64 t; cvta.to.shared.u64 t, %1; cvt.u32.u64 %0, t; }" : "=r"(a) : "l"(p));
    return a;
}
#define SWZ128(o) ((o) ^ (((o) >> 3) & 0x70))

__device__ __forceinline__ void cp16(uint32_t dst, const void* src, uint32_t sz) {
    asm volatile("cp.async.cg.shared.global [%0], [%1], 16, %2;" :: "r"(dst), "l"(src), "r"(sz));
}
__device__ __forceinline__ void ldsm4(uint32_t* r, uint32_t addr) {
    asm volatile("ldmatrix.sync.aligned.m8n8.x4.shared.b16 {%0,%1,%2,%3}, [%4];"
                 : "=r"(r[0]), "=r"(r[1]), "=r"(r[2]), "=r"(r[3]) : "r"(addr));
}
__device__ __forceinline__ void mma16(float* d, const uint32_t* a, const uint32_t* b) {
    asm volatile("mma.sync.aligned.m16n8k16.row.col.f32.bf16.bf16.f32 "
                 "{%0,%1,%2,%3}, {%4,%5,%6,%7}, {%8,%9}, {%0,%1,%2,%3};"
                 : "+f"(d[0]), "+f"(d[1]), "+f"(d[2]), "+f"(d[3])
                 : "r"(a[0]), "r"(a[1]), "r"(a[2]), "r"(a[3]), "r"(b[0]), "r"(b[1]));
}

// ---------------------------------------------------------------------------
// Aux: zero bitmap+counters; mark used entities; build split compact lists.
// ---------------------------------------------------------------------------
__global__ __launch_bounds__(256) void zero_aux() {
    const int i = blockIdx.x * 256 + threadIdx.x;
    if (i < NEMB / 4) ((uint32_t*)g_used)[i] = 0;
    if (i == 0) { g_cnt_u = 0; g_cnt_i = 0; }
}
__global__ __launch_bounds__(256) void mark_used(
    const int* __restrict__ rows, const int* __restrict__ cols) {
    const int i = blockIdx.x * 256 + threadIdx.x;
    g_used[rows[i]] = 1;
    g_used[NUSERS + cols[i]] = 1;
}
__global__ __launch_bounds__(256) void build_list() {
    const int e = blockIdx.x * 256 + threadIdx.x;
    if (e < NEMB && g_used[e]) {
        if (e < NUSERS) { int p = atomicAdd(&g_cnt_u, 1); g_list_u[p] = e; }
        else            { int p = atomicAdd(&g_cnt_i, 1); g_list_i[p] = e; }
    }
}

// ---------------------------------------------------------------------------
// fp32 -> bf16 embedding conversion, USED rows in [row0, row0 + 2*gridDim).
// ---------------------------------------------------------------------------
__global__ __launch_bounds__(256) void conv_emb(
    const float* __restrict__ user_inter, const float* __restrict__ item_inter,
    __nv_bfloat16* __restrict__ Eb, int row0)
{
    const int t = threadIdx.x;
    if (t >= 240) return;
    const int r0 = row0 + blockIdx.x * 2;
    const uchar2 u = *(const uchar2*)(g_used + r0);

    const float* s0 = (r0 < NUSERS) ? user_inter + (size_t)r0 * DIMC
                                    : item_inter + (size_t)(r0 - NUSERS) * DIMC;
    const int r1 = r0 + 1;
    const float* s1 = (r1 < NUSERS) ? user_inter + (size_t)r1 * DIMC
                                    : item_inter + (size_t)(r1 - NUSERS) * DIMC;
    float4 v0, v1;
    if (u.x) v0 = *(const float4*)(s0 + t * 4);
    if (u.y) v1 = *(const float4*)(s1 + t * 4);
    if (u.x) {
        __nv_bfloat16* d = Eb + (size_t)r0 * DIMC + t * 4;
        *(__nv_bfloat162*)(d)     = __nv_bfloat162(__float2bfloat16(v0.x), __float2bfloat16(v0.y));
        *(__nv_bfloat162*)(d + 2) = __nv_bfloat162(__float2bfloat16(v0.z), __float2bfloat16(v0.w));
    }
    if (u.y) {
        __nv_bfloat16* d = Eb + (size_t)r1 * DIMC + t * 4;
        *(__nv_bfloat162*)(d)     = __nv_bfloat162(__float2bfloat16(v1.x), __float2bfloat16(v1.y));
        *(__nv_bfloat162*)(d + 2) = __nv_bfloat162(__float2bfloat16(v1.z), __float2bfloat16(v1.w));
    }
}

// ---------------------------------------------------------------------------
// Wt | W1 | W2 | W3 fp32 -> bf16
// ---------------------------------------------------------------------------
__device__ __forceinline__ void conv_blk(const float* src, __nv_bfloat16* dst, size_t blk) {
    const size_t i = blk * 1024 + threadIdx.x * 4;
    float4 v = *(const float4*)(src + i);
    *(__nv_bfloat162*)(dst + i)     = __nv_bfloat162(__float2bfloat16(v.x), __float2bfloat16(v.y));
    *(__nv_bfloat162*)(dst + i + 2) = __nv_bfloat162(__float2bfloat16(v.z), __float2bfloat16(v.w));
}
__global__ __launch_bounds__(256) void conv_w(
    const float* __restrict__ Wt, const float* __restrict__ W1,
    const float* __restrict__ W2, const float* __restrict__ W3,
    __nv_bfloat16* __restrict__ Wtb, __nv_bfloat16* __restrict__ W1b,
    __nv_bfloat16* __restrict__ W2b, __nv_bfloat16* __restrict__ W3b)
{
    const int b = blockIdx.x;
    if      (b < 900)  conv_blk(Wt, Wtb, b);
    else if (b < 1412) conv_blk(W1, W1b, b - 900);
    else if (b < 1540) conv_blk(W2, W2b, b - 1412);
    else               conv_blk(W3, W3b, b - 1540);
}

// ---------------------------------------------------------------------------
// Transfer GEMM over a compacted row list (R10/R11 mainloop).
// ---------------------------------------------------------------------------
__global__ __launch_bounds__(256) void gemm_tr(
    const __nv_bfloat16* __restrict__ Eb, const __nv_bfloat16* __restrict__ Bw,
    const float* __restrict__ bias, __nv_bfloat16* __restrict__ T,
    const int* __restrict__ list, const int* __restrict__ cntp)
{
    const int cnt = *cntp;
    const int bm = blockIdx.y * 128;
    if (bm >= cnt) return;
    const int bn = blockIdx.x * 128;

    extern __shared__ char smem[];
    const uint32_t base = smem_u32(smem);
    const int t = threadIdx.x;
    const int wid = t >> 5, lane = t & 31;
    const int wm = wid >> 2, wn = wid & 3;
    const int g = lane >> 2, q = lane & 3;

    constexpr int TILE = 16384;
    constexpr int SB   = 2 * TILE;

    float* biass = (float*)(smem);
    int*   idxs  = (int*)(smem + 1024);
    const uint32_t tiles = (base + 3072 + 1023) & ~1023u;

    for (int j = t; j < 128; j += 256) {
        int gn = bn + j;
        biass[j] = (gn < DIMC) ? bias[gn] : 0.f;
        idxs[j]  = (bm + j < cnt) ? list[bm + j] : 0;
    }

    const int seg = t & 7;
    const int rb  = t >> 3;

    int aidx[4]; uint32_t aok[4];
#pragma unroll
    for (int rr = 0; rr < 4; rr++) {
        int gr = bm + rb + rr * 32;
        aok[rr]  = (gr < cnt) ? 16u : 0u;
        aidx[rr] = (gr < cnt) ? list[gr] : 0;
    }

    auto load_chunk = [&](int c, int s) {
        const uint32_t at = tiles + s * SB;
        const uint32_t bt_ = at + TILE;
#pragma unroll
        for (int rr = 0; rr < 4; rr++) {
            int row = rb + rr * 32;
            const __nv_bfloat16* src = Eb + (size_t)aidx[rr] * DIMC + c * 64 + seg * 8;
            cp16(at + SWZ128(row * 128 + seg * 16), src, aok[rr]);
        }
#pragma unroll
        for (int rr = 0; rr < 4; rr++) {
            int row = rb + rr * 32;
            int gn  = bn + row;
            int ok  = gn < DIMC;
            const __nv_bfloat16* src = Bw + (size_t)(ok ? gn : 0) * DIMC + c * 64 + seg * 8;
            cp16(bt_ + SWZ128(row * 128 + seg * 16), src, ok ? 16u : 0u);
        }
        asm volatile("cp.async.commit_group;" ::: "memory");
    };

    float acc[4][4][4];
#pragma unroll
    for (int i = 0; i < 4; i++)
#pragma unroll
        for (int j = 0; j < 4; j++)
#pragma unroll
            for (int v = 0; v < 4; v++) acc[i][j][v] = 0.f;

    const int arow = lane & 15;
    const int aoff = (lane >> 4) * 16;
    const int axor = (arow & 7) << 4;
    const int bm8  = lane >> 3;
    const int brow = ((bm8 >> 1) << 3) + (lane & 7);
    const int boff = (bm8 & 1) * 16;
    const int bxor = (lane & 7) << 4;
    uint32_t off_a[4], off_b[4];
#pragma unroll
    for (int ks = 0; ks < 4; ks++) {
        off_a[ks] = (uint32_t)((wm * 64 + arow) * 128 + ((ks * 32 + aoff) ^ axor));
        off_b[ks] = (uint32_t)((wn * 32 + brow) * 128 + ((ks * 32 + boff) ^ bxor)) + TILE;
    }

    const int NKc = DIMC >> 6;
    load_chunk(0, 0);
    load_chunk(1, 1);

    for (int i = 0; i < NKc; i++) {
        const int s = i - (i / 3) * 3;
        if (i + 1 < NKc) asm volatile("cp.async.wait_group 1;" ::: "memory");
        else             asm volatile("cp.async.wait_group 0;" ::: "memory");
        __syncthreads();
        if (i + 2 < NKc) {
            int s2 = i + 2; s2 -= (s2 / 3) * 3;
            load_chunk(i + 2, s2);
        }

        const uint32_t st = tiles + s * SB;
#pragma unroll
        for (int ks = 0; ks < 4; ks++) {
            uint32_t af[4][4], bf[4][2];
            const uint32_t ab = st + off_a[ks];
            const uint32_t bb = st + off_b[ks];
#pragma unroll
            for (int mt = 0; mt < 4; mt++)
                ldsm4(af[mt], ab + mt * 2048);
#pragma unroll
            for (int np = 0; np < 2; np++) {
                uint32_t r[4];
                ldsm4(r, bb + np * 2048);
                bf[2 * np][0] = r[0]; bf[2 * np][1] = r[1];
                bf[2 * np + 1][0] = r[2]; bf[2 * np + 1][1] = r[3];
            }
#pragma unroll
            for (int mt = 0; mt < 4; mt++)
#pragma unroll
                for (int nt = 0; nt < 4; nt++)
                    mma16(acc[mt][nt], af[mt], bf[nt]);
        }
    }
    __syncthreads();

#pragma unroll
    for (int mt = 0; mt < 4; mt++) {
        const int er0 = wm * 64 + mt * 16 + g;
#pragma unroll
        for (int nt = 0; nt < 4; nt++) {
            const int jc = wn * 32 + nt * 8 + 2 * q;
            const int gn = bn + jc;
            if (gn >= DIMC) continue;
            const float bx = biass[jc], by = biass[jc + 1];
            float x0 = acc[mt][nt][0] + bx, x1 = acc[mt][nt][1] + by;
            float x2 = acc[mt][nt][2] + bx, x3 = acc[mt][nt][3] + by;
            if (bm + er0 < cnt)
                *(__nv_bfloat162*)(T + (size_t)idxs[er0] * DIMC + gn) =
                    __nv_bfloat162(__float2bfloat16(x0), __float2bfloat16(x1));
            if (bm + er0 + 8 < cnt)
                *(__nv_bfloat162*)(T + (size_t)idxs[er0 + 8] * DIMC + gn) =
                    __nv_bfloat162(__float2bfloat16(x2), __float2bfloat16(x3));
        }
    }
}

// ---------------------------------------------------------------------------
// bf16 mma.sync NT GEMM (R8/R11 winner): BM=BN=128, 3-stage cp.async,
// ldmatrix hoisted.  FINAL fuses out[b] = tanh(row).Wr + br + 3.5 (N==128).
// ---------------------------------------------------------------------------
template<bool TANH, bool OUT_BF16, bool FINAL>
__global__ __launch_bounds__(256) void gemm_bf(
    const __nv_bfloat16* __restrict__ A, const __nv_bfloat16* __restrict__ Bw,
    const float* __restrict__ bias, void* __restrict__ Cv,
    const float* __restrict__ Wr, const float* __restrict__ brp,
    int M, int N, int K)
{
    extern __shared__ char smem[];
    const uint32_t base = smem_u32(smem);
    const int t = threadIdx.x;
    const int wid = t >> 5, lane = t & 31;
    const int wm = wid >> 2, wn = wid & 3;
    const int g = lane >> 2, q = lane & 3;

    constexpr int TILE = 16384;
    constexpr int SB   = 2 * TILE;
    const int bm = blockIdx.y * 128;
    const int bn = blockIdx.x * 128;

    float* biass = (float*)(smem);
    float* wrs   = (float*)(smem + 512);
    float* part  = (float*)(smem + 1024);
    const uint32_t tiles = (base + 3072 + 1023) & ~1023u;

    for (int j = t; j < 128; j += 256) {
        int gn = bn + j;
        biass[j] = (gn < N) ? bias[gn] : 0.f;
        if (FINAL) wrs[j] = Wr[j];
    }

    const int seg = t & 7;
    const int rb  = t >> 3;

    auto load_chunk = [&](int c, int s) {
        const uint32_t at = tiles + s * SB;
        const uint32_t bt_ = at + TILE;
#pragma unroll
        for (int rr = 0; rr < 4; rr++) {
            int row = rb + rr * 32;
            int gr  = bm + row;
            int ok  = gr < M;
            const __nv_bfloat16* src = A + (size_t)(ok ? gr : 0) * K + c * 64 + seg * 8;
            cp16(at + SWZ128(row * 128 + seg * 16), src, ok ? 16u : 0u);
        }
#pragma unroll
        for (int rr = 0; rr < 4; rr++) {
            int row = rb + rr * 32;
            int gn  = bn + row;
            int ok  = gn < N;
            const __nv_bfloat16* src = Bw + (size_t)(ok ? gn : 0) * K + c * 64 + seg * 8;
            cp16(bt_ + SWZ128(row * 128 + seg * 16), src, ok ? 16u : 0u);
        }
        asm volatile("cp.async.commit_group;" ::: "memory");
    };

    float acc[4][4][4];
#pragma unroll
    for (int i = 0; i < 4; i++)
#pragma unroll
        for (int j = 0; j < 4; j++)
#pragma unroll
            for (int v = 0; v < 4; v++) acc[i][j][v] = 0.f;

    const int arow = lane & 15;
    const int aoff = (lane >> 4) * 16;
    const int axor = (arow & 7) << 4;
    const int bm8  = lane >> 3;
    const int brow = ((bm8 >> 1) << 3) + (lane & 7);
    const int boff = (bm8 & 1) * 16;
    const int bxor = (lane & 7) << 4;
    uint32_t off_a[4], off_b[4];
#pragma unroll
    for (int ks = 0; ks < 4; ks++) {
        off_a[ks] = (uint32_t)((wm * 64 + arow) * 128 + ((ks * 32 + aoff) ^ axor));
        off_b[ks] = (uint32_t)((wn * 32 + brow) * 128 + ((ks * 32 + boff) ^ bxor)) + TILE;
    }

    const int NKc = K >> 6;
    load_chunk(0, 0);
    load_chunk(1, 1);

    for (int i = 0; i < NKc; i++) {
        const int s = i - (i / 3) * 3;
        if (i + 1 < NKc) asm volatile("cp.async.wait_group 1;" ::: "memory");
        else             asm volatile("cp.async.wait_group 0;" ::: "memory");
        __syncthreads();
        if (i + 2 < NKc) {
            int s2 = i + 2; s2 -= (s2 / 3) * 3;
            load_chunk(i + 2, s2);
        }

        const uint32_t st = tiles + s * SB;
#pragma unroll
        for (int ks = 0; ks < 4; ks++) {
            uint32_t af[4][4], bf[4][2];
            const uint32_t ab = st + off_a[ks];
            const uint32_t bb = st + off_b[ks];
#pragma unroll
            for (int mt = 0; mt < 4; mt++)
                ldsm4(af[mt], ab + mt * 2048);
#pragma unroll
            for (int np = 0; np < 2; np++) {
                uint32_t r[4];
                ldsm4(r, bb + np * 2048);
                bf[2 * np][0] = r[0]; bf[2 * np][1] = r[1];
                bf[2 * np + 1][0] = r[2]; bf[2 * np + 1][1] = r[3];
            }
#pragma unroll
            for (int mt = 0; mt < 4; mt++)
#pragma unroll
                for (int nt = 0; nt < 4; nt++)
                    mma16(acc[mt][nt], af[mt], bf[nt]);
        }
    }
    __syncthreads();

    if (FINAL) {
#pragma unroll
        for (int mt = 0; mt < 4; mt++) {
            float p0 = 0.f, p1 = 0.f;
#pragma unroll
            for (int nt = 0; nt < 4; nt++) {
                const int jc = wn * 32 + nt * 8 + 2 * q;
                const float bx = biass[jc], by = biass[jc + 1];
                const float wx = wrs[jc],  wy = wrs[jc + 1];
                p0 += tanhf(acc[mt][nt][0] + bx) * wx + tanhf(acc[mt][nt][1] + by) * wy;
                p1 += tanhf(acc[mt][nt][2] + bx) * wx + tanhf(acc[mt][nt][3] + by) * wy;
            }
            p0 += __shfl_xor_sync(0xFFFFFFFFu, p0, 1);
            p0 += __shfl_xor_sync(0xFFFFFFFFu, p0, 2);
            p1 += __shfl_xor_sync(0xFFFFFFFFu, p1, 1);
            p1 += __shfl_xor_sync(0xFFFFFFFFu, p1, 2);
            if (q == 0) {
                part[(wm * 64 + mt * 16 + g) * 4 + wn]     = p0;
                part[(wm * 64 + mt * 16 + g + 8) * 4 + wn] = p1;
            }
        }
        __syncthreads();
        if (t < 128) {
            float s = part[t * 4] + part[t * 4 + 1] + part[t * 4 + 2] + part[t * 4 + 3];
            if (bm + t < M) ((float*)Cv)[bm + t] = s + brp[0] + 3.5f;
        }
        return;
    }

#pragma unroll
    for (int mt = 0; mt < 4; mt++) {
        const int r0 = bm + wm * 64 + mt * 16 + g;
#pragma unroll
        for (int nt = 0; nt < 4; nt++) {
            const int jc = wn * 32 + nt * 8 + 2 * q;
            const int gn = bn + jc;
            if (gn >= N) continue;
            const float bx = biass[jc], by = biass[jc + 1];
            float x0 = acc[mt][nt][0] + bx, x1 = acc[mt][nt][1] + by;
            float x2 = acc[mt][nt][2] + bx, x3 = acc[mt][nt][3] + by;
            if (TANH) { x0 = tanhf(x0); x1 = tanhf(x1); x2 = tanhf(x2); x3 = tanhf(x3); }
            if (OUT_BF16) {
                __nv_bfloat16* C = (__nv_bfloat16*)Cv;
                if (r0 < M)
                    *(__nv_bfloat162*)(C + (size_t)r0 * N + gn) =
                        __nv_bfloat162(__float2bfloat16(x0), __float2bfloat16(x1));
                if (r0 + 8 < M)
                    *(__nv_bfloat162*)(C + (size_t)(r0 + 8) * N + gn) =
                        __nv_bfloat162(__float2bfloat16(x2), __float2bfloat16(x3));
            } else {
                float* C = (float*)Cv;
                if (r0 < M)     *(float2*)(C + (size_t)r0 * N + gn)       = make_float2(x0, x1);
                if (r0 + 8 < M) *(float2*)(C + (size_t)(r0 + 8) * N + gn) = make_float2(x2, x3);
            }
        }
    }
}

// ---------------------------------------------------------------------------
// Gather + elementwise product + concat into F0[B, 1024] (bf16) -- R11.
// ---------------------------------------------------------------------------
__global__ __launch_bounds__(256) void build_factor(
    const int* __restrict__ rows, const int* __restrict__ cols,
    const float* __restrict__ uix, const float* __restrict__ iix,
    const __nv_bfloat16* __restrict__ T, __nv_bfloat16* __restrict__ F0)
{
    const int b0 = blockIdx.x * BF_E;
    const int t  = threadIdx.x;
    const int f  = t * 4;

    int rr[BF_E], cc[BF_E];
    {
        int4 ra = *(const int4*)(rows + b0);
        int4 rb_ = *(const int4*)(rows + b0 + 4);
        int4 ca = *(const int4*)(cols + b0);
        int4 cb = *(const int4*)(cols + b0 + 4);
        rr[0] = ra.x; rr[1] = ra.y; rr[2] = ra.z; rr[3] = ra.w;
        rr[4] = rb_.x; rr[5] = rb_.y; rr[6] = rb_.z; rr[7] = rb_.w;
        cc[0] = ca.x; cc[1] = ca.y; cc[2] = ca.z; cc[3] = ca.w;
        cc[4] = cb.x; cc[5] = cb.y; cc[6] = cb.z; cc[7] = cb.w;
    }

    if (f < 32) {
        float4 v[BF_E];
#pragma unroll
        for (int e = 0; e < BF_E; e++)
            v[e] = *(const float4*)(uix + (size_t)rr[e] * DIMS + f);
#pragma unroll
        for (int e = 0; e < BF_E; e++) {
            __nv_bfloat16* o = F0 + (size_t)(b0 + e) * 1024 + f;
            *(__nv_bfloat162*)(o)     = __nv_bfloat162(__float2bfloat16(v[e].x), __float2bfloat16(v[e].y));
            *(__nv_bfloat162*)(o + 2) = __nv_bfloat162(__float2bfloat16(v[e].z), __float2bfloat16(v[e].w));
        }
    } else if (f < 64) {
        float4 v[BF_E];
#pragma unroll
        for (int e = 0; e < BF_E; e++)
            v[e] = *(const float4*)(iix + (size_t)cc[e] * DIMS + (f - 32));
#pragma unroll
        for (int e = 0; e < BF_E; e++) {
            __nv_bfloat16* o = F0 + (size_t)(b0 + e) * 1024 + f;
            *(__nv_bfloat162*)(o)     = __nv_bfloat162(__float2bfloat16(v[e].x), __float2bfloat16(v[e].y));
            *(__nv_bfloat162*)(o + 2) = __nv_bfloat162(__float2bfloat16(v[e].z), __float2bfloat16(v[e].w));
        }
    } else {
        uint2 av[BF_E], bv[BF_E];
#pragma unroll
        for (int e = 0; e < BF_E; e++)
            av[e] = *(const uint2*)(T + (size_t)rr[e] * DIMC + (f - 64));
#pragma unroll
        for (int e = 0; e < BF_E; e++)
            bv[e] = *(const uint2*)(T + (size_t)(NUSERS + cc[e]) * DIMC + (f - 64));
#pragma unroll
        for (int e = 0; e < BF_E; e++) {
            __nv_bfloat162 a0 = *(__nv_bfloat162*)&av[e].x;
            __nv_bfloat162 a1 = *(__nv_bfloat162*)&av[e].y;
            __nv_bfloat162 b0_ = *(__nv_bfloat162*)&bv[e].x;
            __nv_bfloat162 b1_ = *(__nv_bfloat162*)&bv[e].y;
            __nv_bfloat162 p0 = __hmul2(a0, b0_);
            __nv_bfloat162 p1 = __hmul2(a1, b1_);
            uint2 w;
            w.x = *(uint32_t*)&p0;
            w.y = *(uint32_t*)&p1;
            *(uint2*)(F0 + (size_t)(b0 + e) * 1024 + f) = w;
        }
    }
}

// ---------------------------------------------------------------------------
extern "C" void kernel_launch(void* const* d_in, const int* in_sizes, int n_in,
                              void* d_out, int out_size)
{
    const int*   rows       = (const int*)d_in[0];
    const int*   cols       = (const int*)d_in[1];
    const float* user_inter = (const float*)d_in[2];
    const float* item_inter = (const float*)d_in[3];
    const float* uix        = (const float*)d_in[4];
    const float* iix        = (const float*)d_in[5];
    const float* Wt         = (const float*)d_in[6];
    const float* bt         = (const float*)d_in[7];
    const float* W1         = (const float*)d_in[8];
    const float* b1         = (const float*)d_in[9];
    const float* W2         = (const float*)d_in[10];
    const float* b2         = (const float*)d_in[11];
    const float* W3         = (const float*)d_in[12];
    const float* b3         = (const float*)d_in[13];
    const float* Wr         = (const float*)d_in[14];
    const float* br         = (const float*)d_in[15];
    float*       out        = (float*)d_out;

    __nv_bfloat16 *Eb, *Wtb, *T, *W1b, *W2b, *W3b, *F0, *F1, *F2;
    int *Lu, *Li, *Cu, *Ci;
    cudaGetSymbolAddress((void**)&Eb,  g_Eb);
    cudaGetSymbolAddress((void**)&Wtb, g_Wtb);
    cudaGetSymbolAddress((void**)&T,   g_T);
    cudaGetSymbolAddress((void**)&W1b, g_W1b);
    cudaGetSymbolAddress((void**)&W2b, g_W2b);
    cudaGetSymbolAddress((void**)&W3b, g_W3b);
    cudaGetSymbolAddress((void**)&F0,  g_F0);
    cudaGetSymbolAddress((void**)&F1,  g_F1);
    cudaGetSymbolAddress((void**)&F2,  g_F2);
    cudaGetSymbolAddress((void**)&Lu,  g_list_u);
    cudaGetSymbolAddress((void**)&Li,  g_list_i);
    cudaGetSymbolAddress((void**)&Cu,  g_cnt_u);
    cudaGetSymbolAddress((void**)&Ci,  g_cnt_i);

    static cudaStream_t s1 = nullptr;
    static cudaEvent_t evFork, evM, evCu, evL, evTu, evTi, evB;
    if (!s1) {
        cudaStreamCreateWithFlags(&s1, cudaStreamNonBlocking);
        cudaEventCreateWithFlags(&evFork, cudaEventDisableTiming);
        cudaEventCreateWithFlags(&evM,    cudaEventDisableTiming);
        cudaEventCreateWithFlags(&evCu,   cudaEventDisableTiming);
        cudaEventCreateWithFlags(&evL,    cudaEventDisableTiming);
        cudaEventCreateWithFlags(&evTu,   cudaEventDisableTiming);
        cudaEventCreateWithFlags(&evTi,   cudaEventDisableTiming);
        cudaEventCreateWithFlags(&evB,    cudaEventDisableTiming);
    }

    const int SZ = 3072 + 1024 + 3 * 32768;   // 102400
    cudaFuncSetAttribute(gemm_tr, cudaFuncAttributeMaxDynamicSharedMemorySize, SZ);
    cudaFuncSetAttribute(gemm_bf<true, true, false>,  cudaFuncAttributeMaxDynamicSharedMemorySize, SZ);
    cudaFuncSetAttribute(gemm_bf<true, false, true>,  cudaFuncAttributeMaxDynamicSharedMemorySize, SZ);

    const dim3 blk(256);
    cudaStream_t s0 = 0;

    // ---- fork ----
    cudaEventRecord(evFork, s0);
    cudaStreamWaitEvent(s1, evFork, 0);

    // s1: weight conversions (independent)
    conv_w<<<1572, blk, 0, s1>>>(Wt, W1, W2, W3, Wtb, W1b, W2b, W3b);

    // s0: zero + mark
    zero_aux<<<147, blk, 0, s0>>>();
    mark_used<<<NB / 256, blk, 0, s0>>>(rows, cols);
    cudaEventRecord(evM, s0);

    // s1: build split lists (needs mark)
    cudaStreamWaitEvent(s1, evM, 0);
    build_list<<<(NEMB + 255) / 256, blk, 0, s1>>>();
    cudaEventRecord(evL, s1);

    // s0: convert USER rows, then user transfer GEMM immediately
    conv_emb<<<NUSERS / 2, blk, 0, s0>>>(user_inter, item_inter, Eb, 0);
    cudaEventRecord(evCu, s0);
    cudaStreamWaitEvent(s0, evL, 0);
    gemm_tr<<<dim3(8, (NUSERS + 127) / 128), blk, SZ, s0>>>(Eb, Wtb, bt, T, Lu, Cu);
    cudaEventRecord(evTu, s0);

    // s1: convert ITEM rows under gemm_u, then item transfer GEMM
    cudaStreamWaitEvent(s1, evCu, 0);      // serialize convs (both DRAM-bound)
    conv_emb<<<NITEMS / 2, blk, 0, s1>>>(user_inter, item_inter, Eb, NUSERS);
    gemm_tr<<<dim3(8, (NITEMS + 127) / 128), blk, SZ, s1>>>(Eb, Wtb, bt, T, Li, Ci);
    cudaEventRecord(evTi, s1);

    // ---- two batch-half chains (need BOTH transfer GEMMs) ----
    cudaStreamWaitEvent(s0, evTi, 0);
    build_factor<<<NBH / BF_E, blk, 0, s0>>>(rows, cols, uix, iix, T, F0);
    gemm_bf<true, true, false><<<dim3(4, NBH / 128), blk, SZ, s0>>>(
        F0, W1b, b1, F1, nullptr, nullptr, NBH, 512, 1024);
    gemm_bf<true, true, false><<<dim3(2, NBH / 128), blk, SZ, s0>>>(
        F1, W2b, b2, F2, nullptr, nullptr, NBH, 256, 512);
    gemm_bf<true, false, true><<<dim3(1, NBH / 128), blk, SZ, s0>>>(
        F2, W3b, b3, out, Wr, br, NBH, 128, 256);

    cudaStreamWaitEvent(s1, evTu, 0);
    build_factor<<<NBH / BF_E, blk, 0, s1>>>(
        rows + NBH, cols + NBH, uix, iix, T, F0 + (size_t)NBH * 1024);
    gemm_bf<true, true, false><<<dim3(4, NBH / 128), blk, SZ, s1>>>(
        F0 + (size_t)NBH * 1024, W1b, b1, F1 + (size_t)NBH * 512,
        nullptr, nullptr, NBH, 512, 1024);
    gemm_bf<true, true, false><<<dim3(2, NBH / 128), blk, SZ, s1>>>(
        F1 + (size_t)NBH * 512, W2b, b2, F2 + (size_t)NBH * 256,
        nullptr, nullptr, NBH, 256, 512);
    gemm_bf<true, false, true><<<dim3(1, NBH / 128), blk, SZ, s1>>>(
        F2 + (size_t)NBH * 256, W3b, b3, out + NBH, Wr, br, NBH, 128, 256);
    cudaEventRecord(evB, s1);

    // ---- join ----
    cudaStreamWaitEvent(s0, evB, 0);
}

// round 15
// speedup vs baseline: 1.0081x; 1.0081x over previous
#include <cuda_runtime.h>
#include <cuda_bf16.h>
#include <cstdint>
#include <cstddef>

// ===========================================================================
// DaConA on GB300 (sm_103 PTX target: mma.sync bf16 HMMA k16 + ldmatrix with
// hoisted swizzle addressing).  R13 winner schedule (dual-stream fork-join:
// conv_w/build_list on side stream; MLP split into two batch halves) with
// micro-tuned aux kernels.
// pred = MLP(concat(u_indep[r], i_indep[c], (Wt@u[r]+bt)*(Wt@i[c]+bt))) + 3.5
// ===========================================================================

#define NB      131072
#define NUSERS  100000
#define NITEMS  50000
#define NEMB    150000
#define DIMC    960
#define DIMS    32
#define BF_E    8
#define NBH     (NB / 2)

__device__ __nv_bfloat16 g_Eb[(size_t)NEMB * DIMC];
__device__ __nv_bfloat16 g_Wtb[(size_t)DIMC * DIMC];
__device__ __nv_bfloat16 g_T [(size_t)NEMB * DIMC];
__device__ __nv_bfloat16 g_W1b[512 * 1024];
__device__ __nv_bfloat16 g_W2b[256 * 512];
__device__ __nv_bfloat16 g_W3b[128 * 256];
__device__ __nv_bfloat16 g_F0[(size_t)NB * 1024];
__device__ __nv_bfloat16 g_F1[(size_t)NB * 512];
__device__ __nv_bfloat16 g_F2[(size_t)NB * 256];
__device__ unsigned char g_used[NEMB];
__device__ int g_list[NEMB];
__device__ int g_cnt;

__device__ __forceinline__ uint32_t smem_u32(const void* p) {
    uint32_t a;
    asm("{ .reg .u64 t; cvta.to.shared.u64 t, %1; cvt.u32.u64 %0, t; }" : "=r"(a) : "l"(p));
    return a;
}
#define SWZ128(o) ((o) ^ (((o) >> 3) & 0x70))

__device__ __forceinline__ void cp16(uint32_t dst, const void* src, uint32_t sz) {
    asm volatile("cp.async.cg.shared.global [%0], [%1], 16, %2;" :: "r"(dst), "l"(src), "r"(sz));
}
__device__ __forceinline__ void ldsm4(uint32_t* r, uint32_t addr) {
    asm volatile("ldmatrix.sync.aligned.m8n8.x4.shared.b16 {%0,%1,%2,%3}, [%4];"
                 : "=r"(r[0]), "=r"(r[1]), "=r"(r[2]), "=r"(r[3]) : "r"(addr));
}
__device__ __forceinline__ void mma16(float* d, const uint32_t* a, const uint32_t* b) {
    asm volatile("mma.sync.aligned.m16n8k16.row.col.f32.bf16.bf16.f32 "
                 "{%0,%1,%2,%3}, {%4,%5,%6,%7}, {%8,%9}, {%0,%1,%2,%3};"
                 : "+f"(d[0]), "+f"(d[1]), "+f"(d[2]), "+f"(d[3])
                 : "r"(a[0]), "r"(a[1]), "r"(a[2]), "r"(a[3]), "r"(b[0]), "r"(b[1]));
}

// ---------------------------------------------------------------------------
// Aux: zero bitmap+counter; mark used entities; build compact list.
// ---------------------------------------------------------------------------
__global__ __launch_bounds__(256) void zero_aux() {
    const int i = blockIdx.x * 256 + threadIdx.x;
#pragma unroll
    for (int k = 0; k < 4; k++) {
        int j = i + k * 9472;                   // 37 blocks * 256
        if (j < NEMB / 4) ((uint32_t*)g_used)[j] = 0;
    }
    if (i == 0) g_cnt = 0;
}
__global__ __launch_bounds__(256) void mark_used(
    const int* __restrict__ rows, const int* __restrict__ cols) {
    const int i = (blockIdx.x * 256 + threadIdx.x) * 2;
    int2 r = *(const int2*)(rows + i);
    int2 c = *(const int2*)(cols + i);
    g_used[r.x] = 1;
    g_used[r.y] = 1;
    g_used[NUSERS + c.x] = 1;
    g_used[NUSERS + c.y] = 1;
}
__global__ __launch_bounds__(256) void build_list() {
    const int e = blockIdx.x * 256 + threadIdx.x;
    if (e < NEMB && g_used[e]) {
        int p = atomicAdd(&g_cnt, 1);
        g_list[p] = e;
    }
}

// ---------------------------------------------------------------------------
// fp32 -> bf16 embedding conversion, USED rows only.
// ---------------------------------------------------------------------------
__global__ __launch_bounds__(256) void conv_emb(
    const float* __restrict__ user_inter, const float* __restrict__ item_inter,
    __nv_bfloat16* __restrict__ Eb)
{
    const int t = threadIdx.x;
    if (t >= 240) return;
    const int r0 = blockIdx.x * 2;
    const uchar2 u = *(const uchar2*)(g_used + r0);

    const float* s0 = (r0 < NUSERS) ? user_inter + (size_t)r0 * DIMC
                                    : item_inter + (size_t)(r0 - NUSERS) * DIMC;
    const int r1 = r0 + 1;
    const float* s1 = (r1 < NUSERS) ? user_inter + (size_t)r1 * DIMC
                                    : item_inter + (size_t)(r1 - NUSERS) * DIMC;
    float4 v0, v1;
    if (u.x) v0 = *(const float4*)(s0 + t * 4);
    if (u.y) v1 = *(const float4*)(s1 + t * 4);
    if (u.x) {
        __nv_bfloat16* d = Eb + (size_t)r0 * DIMC + t * 4;
        *(__nv_bfloat162*)(d)     = __nv_bfloat162(__float2bfloat16(v0.x), __float2bfloat16(v0.y));
        *(__nv_bfloat162*)(d + 2) = __nv_bfloat162(__float2bfloat16(v0.z), __float2bfloat16(v0.w));
    }
    if (u.y) {
        __nv_bfloat16* d = Eb + (size_t)r1 * DIMC + t * 4;
        *(__nv_bfloat162*)(d)     = __nv_bfloat162(__float2bfloat16(v1.x), __float2bfloat16(v1.y));
        *(__nv_bfloat162*)(d + 2) = __nv_bfloat162(__float2bfloat16(v1.z), __float2bfloat16(v1.w));
    }
}

// ---------------------------------------------------------------------------
// Wt | W1 | W2 | W3 fp32 -> bf16
// ---------------------------------------------------------------------------
__device__ __forceinline__ void conv_blk(const float* src, __nv_bfloat16* dst, size_t blk) {
    const size_t i = blk * 1024 + threadIdx.x * 4;
    float4 v = *(const float4*)(src + i);
    *(__nv_bfloat162*)(dst + i)     = __nv_bfloat162(__float2bfloat16(v.x), __float2bfloat16(v.y));
    *(__nv_bfloat162*)(dst + i + 2) = __nv_bfloat162(__float2bfloat16(v.z), __float2bfloat16(v.w));
}
__global__ __launch_bounds__(256) void conv_w(
    const float* __restrict__ Wt, const float* __restrict__ W1,
    const float* __restrict__ W2, const float* __restrict__ W3,
    __nv_bfloat16* __restrict__ Wtb, __nv_bfloat16* __restrict__ W1b,
    __nv_bfloat16* __restrict__ W2b, __nv_bfloat16* __restrict__ W3b)
{
    const int b = blockIdx.x;
    if      (b < 900)  conv_blk(Wt, Wtb, b);
    else if (b < 1412) conv_blk(W1, W1b, b - 900);
    else if (b < 1540) conv_blk(W2, W2b, b - 1412);
    else               conv_blk(W3, W3b, b - 1540);
}

// ---------------------------------------------------------------------------
// Transfer GEMM over COMPACTED rows (R10/R11 mainloop).
// ---------------------------------------------------------------------------
__global__ __launch_bounds__(256) void gemm_tr(
    const __nv_bfloat16* __restrict__ Eb, const __nv_bfloat16* __restrict__ Bw,
    const float* __restrict__ bias, __nv_bfloat16* __restrict__ T)
{
    const int cnt = g_cnt;
    const int bm = blockIdx.y * 128;
    if (bm >= cnt) return;
    const int bn = blockIdx.x * 128;

    extern __shared__ char smem[];
    const uint32_t base = smem_u32(smem);
    const int t = threadIdx.x;
    const int wid = t >> 5, lane = t & 31;
    const int wm = wid >> 2, wn = wid & 3;
    const int g = lane >> 2, q = lane & 3;

    constexpr int TILE = 16384;
    constexpr int SB   = 2 * TILE;

    float* biass = (float*)(smem);
    int*   idxs  = (int*)(smem + 1024);
    const uint32_t tiles = (base + 3072 + 1023) & ~1023u;

    for (int j = t; j < 128; j += 256) {
        int gn = bn + j;
        biass[j] = (gn < DIMC) ? bias[gn] : 0.f;
        idxs[j]  = (bm + j < cnt) ? __ldg(g_list + bm + j) : 0;
    }

    const int seg = t & 7;
    const int rb  = t >> 3;

    int aidx[4]; uint32_t aok[4];
#pragma unroll
    for (int rr = 0; rr < 4; rr++) {
        int gr = bm + rb + rr * 32;
        aok[rr]  = (gr < cnt) ? 16u : 0u;
        aidx[rr] = (gr < cnt) ? __ldg(g_list + gr) : 0;
    }

    auto load_chunk = [&](int c, int s) {
        const uint32_t at = tiles + s * SB;
        const uint32_t bt_ = at + TILE;
#pragma unroll
        for (int rr = 0; rr < 4; rr++) {
            int row = rb + rr * 32;
            const __nv_bfloat16* src = Eb + (size_t)aidx[rr] * DIMC + c * 64 + seg * 8;
            cp16(at + SWZ128(row * 128 + seg * 16), src, aok[rr]);
        }
#pragma unroll
        for (int rr = 0; rr < 4; rr++) {
            int row = rb + rr * 32;
            int gn  = bn + row;
            int ok  = gn < DIMC;
            const __nv_bfloat16* src = Bw + (size_t)(ok ? gn : 0) * DIMC + c * 64 + seg * 8;
            cp16(bt_ + SWZ128(row * 128 + seg * 16), src, ok ? 16u : 0u);
        }
        asm volatile("cp.async.commit_group;" ::: "memory");
    };

    float acc[4][4][4];
#pragma unroll
    for (int i = 0; i < 4; i++)
#pragma unroll
        for (int j = 0; j < 4; j++)
#pragma unroll
            for (int v = 0; v < 4; v++) acc[i][j][v] = 0.f;

    const int arow = lane & 15;
    const int aoff = (lane >> 4) * 16;
    const int axor = (arow & 7) << 4;
    const int bm8  = lane >> 3;
    const int brow = ((bm8 >> 1) << 3) + (lane & 7);
    const int boff = (bm8 & 1) * 16;
    const int bxor = (lane & 7) << 4;
    uint32_t off_a[4], off_b[4];
#pragma unroll
    for (int ks = 0; ks < 4; ks++) {
        off_a[ks] = (uint32_t)((wm * 64 + arow) * 128 + ((ks * 32 + aoff) ^ axor));
        off_b[ks] = (uint32_t)((wn * 32 + brow) * 128 + ((ks * 32 + boff) ^ bxor)) + TILE;
    }

    const int NKc = DIMC >> 6;
    load_chunk(0, 0);
    load_chunk(1, 1);

    for (int i = 0; i < NKc; i++) {
        const int s = i - (i / 3) * 3;
        if (i + 1 < NKc) asm volatile("cp.async.wait_group 1;" ::: "memory");
        else             asm volatile("cp.async.wait_group 0;" ::: "memory");
        __syncthreads();
        if (i + 2 < NKc) {
            int s2 = i + 2; s2 -= (s2 / 3) * 3;
            load_chunk(i + 2, s2);
        }

        const uint32_t st = tiles + s * SB;
#pragma unroll
        for (int ks = 0; ks < 4; ks++) {
            uint32_t af[4][4], bf[4][2];
            const uint32_t ab = st + off_a[ks];
            const uint32_t bb = st + off_b[ks];
#pragma unroll
            for (int mt = 0; mt < 4; mt++)
                ldsm4(af[mt], ab + mt * 2048);
#pragma unroll
            for (int np = 0; np < 2; np++) {
                uint32_t r[4];
                ldsm4(r, bb + np * 2048);
                bf[2 * np][0] = r[0]; bf[2 * np][1] = r[1];
                bf[2 * np + 1][0] = r[2]; bf[2 * np + 1][1] = r[3];
            }
#pragma unroll
            for (int mt = 0; mt < 4; mt++)
#pragma unroll
                for (int nt = 0; nt < 4; nt++)
                    mma16(acc[mt][nt], af[mt], bf[nt]);
        }
    }
    __syncthreads();

#pragma unroll
    for (int mt = 0; mt < 4; mt++) {
        const int er0 = wm * 64 + mt * 16 + g;
#pragma unroll
        for (int nt = 0; nt < 4; nt++) {
            const int jc = wn * 32 + nt * 8 + 2 * q;
            const int gn = bn + jc;
            if (gn >= DIMC) continue;
            const float bx = biass[jc], by = biass[jc + 1];
            float x0 = acc[mt][nt][0] + bx, x1 = acc[mt][nt][1] + by;
            float x2 = acc[mt][nt][2] + bx, x3 = acc[mt][nt][3] + by;
            if (bm + er0 < cnt)
                *(__nv_bfloat162*)(T + (size_t)idxs[er0] * DIMC + gn) =
                    __nv_bfloat162(__float2bfloat16(x0), __float2bfloat16(x1));
            if (bm + er0 + 8 < cnt)
                *(__nv_bfloat162*)(T + (size_t)idxs[er0 + 8] * DIMC + gn) =
                    __nv_bfloat162(__float2bfloat16(x2), __float2bfloat16(x3));
        }
    }
}

// ---------------------------------------------------------------------------
// bf16 mma.sync NT GEMM (R8/R11 winner): BM=BN=128, 3-stage cp.async,
// ldmatrix hoisted.  FINAL fuses out[b] = tanh(row).Wr + br + 3.5 (N==128).
// ---------------------------------------------------------------------------
template<bool TANH, bool OUT_BF16, bool FINAL>
__global__ __launch_bounds__(256) void gemm_bf(
    const __nv_bfloat16* __restrict__ A, const __nv_bfloat16* __restrict__ Bw,
    const float* __restrict__ bias, void* __restrict__ Cv,
    const float* __restrict__ Wr, const float* __restrict__ brp,
    int M, int N, int K)
{
    extern __shared__ char smem[];
    const uint32_t base = smem_u32(smem);
    const int t = threadIdx.x;
    const int wid = t >> 5, lane = t & 31;
    const int wm = wid >> 2, wn = wid & 3;
    const int g = lane >> 2, q = lane & 3;

    constexpr int TILE = 16384;
    constexpr int SB   = 2 * TILE;
    const int bm = blockIdx.y * 128;
    const int bn = blockIdx.x * 128;

    float* biass = (float*)(smem);
    float* wrs   = (float*)(smem + 512);
    float* part  = (float*)(smem + 1024);
    const uint32_t tiles = (base + 3072 + 1023) & ~1023u;

    for (int j = t; j < 128; j += 256) {
        int gn = bn + j;
        biass[j] = (gn < N) ? bias[gn] : 0.f;
        if (FINAL) wrs[j] = Wr[j];
    }

    const int seg = t & 7;
    const int rb  = t >> 3;

    auto load_chunk = [&](int c, int s) {
        const uint32_t at = tiles + s * SB;
        const uint32_t bt_ = at + TILE;
#pragma unroll
        for (int rr = 0; rr < 4; rr++) {
            int row = rb + rr * 32;
            int gr  = bm + row;
            int ok  = gr < M;
            const __nv_bfloat16* src = A + (size_t)(ok ? gr : 0) * K + c * 64 + seg * 8;
            cp16(at + SWZ128(row * 128 + seg * 16), src, ok ? 16u : 0u);
        }
#pragma unroll
        for (int rr = 0; rr < 4; rr++) {
            int row = rb + rr * 32;
            int gn  = bn + row;
            int ok  = gn < N;
            const __nv_bfloat16* src = Bw + (size_t)(ok ? gn : 0) * K + c * 64 + seg * 8;
            cp16(bt_ + SWZ128(row * 128 + seg * 16), src, ok ? 16u : 0u);
        }
        asm volatile("cp.async.commit_group;" ::: "memory");
    };

    float acc[4][4][4];
#pragma unroll
    for (int i = 0; i < 4; i++)
#pragma unroll
        for (int j = 0; j < 4; j++)
#pragma unroll
            for (int v = 0; v < 4; v++) acc[i][j][v] = 0.f;

    const int arow = lane & 15;
    const int aoff = (lane >> 4) * 16;
    const int axor = (arow & 7) << 4;
    const int bm8  = lane >> 3;
    const int brow = ((bm8 >> 1) << 3) + (lane & 7);
    const int boff = (bm8 & 1) * 16;
    const int bxor = (lane & 7) << 4;
    uint32_t off_a[4], off_b[4];
#pragma unroll
    for (int ks = 0; ks < 4; ks++) {
        off_a[ks] = (uint32_t)((wm * 64 + arow) * 128 + ((ks * 32 + aoff) ^ axor));
        off_b[ks] = (uint32_t)((wn * 32 + brow) * 128 + ((ks * 32 + boff) ^ bxor)) + TILE;
    }

    const int NKc = K >> 6;
    load_chunk(0, 0);
    load_chunk(1, 1);

    for (int i = 0; i < NKc; i++) {
        const int s = i - (i / 3) * 3;
        if (i + 1 < NKc) asm volatile("cp.async.wait_group 1;" ::: "memory");
        else             asm volatile("cp.async.wait_group 0;" ::: "memory");
        __syncthreads();
        if (i + 2 < NKc) {
            int s2 = i + 2; s2 -= (s2 / 3) * 3;
            load_chunk(i + 2, s2);
        }

        const uint32_t st = tiles + s * SB;
#pragma unroll
        for (int ks = 0; ks < 4; ks++) {
            uint32_t af[4][4], bf[4][2];
            const uint32_t ab = st + off_a[ks];
            const uint32_t bb = st + off_b[ks];
#pragma unroll
            for (int mt = 0; mt < 4; mt++)
                ldsm4(af[mt], ab + mt * 2048);
#pragma unroll
            for (int np = 0; np < 2; np++) {
                uint32_t r[4];
                ldsm4(r, bb + np * 2048);
                bf[2 * np][0] = r[0]; bf[2 * np][1] = r[1];
                bf[2 * np + 1][0] = r[2]; bf[2 * np + 1][1] = r[3];
            }
#pragma unroll
            for (int mt = 0; mt < 4; mt++)
#pragma unroll
                for (int nt = 0; nt < 4; nt++)
                    mma16(acc[mt][nt], af[mt], bf[nt]);
        }
    }
    __syncthreads();

    if (FINAL) {
#pragma unroll
        for (int mt = 0; mt < 4; mt++) {
            float p0 = 0.f, p1 = 0.f;
#pragma unroll
            for (int nt = 0; nt < 4; nt++) {
                const int jc = wn * 32 + nt * 8 + 2 * q;
                const float bx = biass[jc], by = biass[jc + 1];
                const float wx = wrs[jc],  wy = wrs[jc + 1];
                p0 += tanhf(acc[mt][nt][0] + bx) * wx + tanhf(acc[mt][nt][1] + by) * wy;
                p1 += tanhf(acc[mt][nt][2] + bx) * wx + tanhf(acc[mt][nt][3] + by) * wy;
            }
            p0 += __shfl_xor_sync(0xFFFFFFFFu, p0, 1);
            p0 += __shfl_xor_sync(0xFFFFFFFFu, p0, 2);
            p1 += __shfl_xor_sync(0xFFFFFFFFu, p1, 1);
            p1 += __shfl_xor_sync(0xFFFFFFFFu, p1, 2);
            if (q == 0) {
                part[(wm * 64 + mt * 16 + g) * 4 + wn]     = p0;
                part[(wm * 64 + mt * 16 + g + 8) * 4 + wn] = p1;
            }
        }
        __syncthreads();
        if (t < 128) {
            float s = part[t * 4] + part[t * 4 + 1] + part[t * 4 + 2] + part[t * 4 + 3];
            if (bm + t < M) ((float*)Cv)[bm + t] = s + brp[0] + 3.5f;
        }
        return;
    }

#pragma unroll
    for (int mt = 0; mt < 4; mt++) {
        const int r0 = bm + wm * 64 + mt * 16 + g;
#pragma unroll
        for (int nt = 0; nt < 4; nt++) {
            const int jc = wn * 32 + nt * 8 + 2 * q;
            const int gn = bn + jc;
            if (gn >= N) continue;
            const float bx = biass[jc], by = biass[jc + 1];
            float x0 = acc[mt][nt][0] + bx, x1 = acc[mt][nt][1] + by;
            float x2 = acc[mt][nt][2] + bx, x3 = acc[mt][nt][3] + by;
            if (TANH) { x0 = tanhf(x0); x1 = tanhf(x1); x2 = tanhf(x2); x3 = tanhf(x3); }
            if (OUT_BF16) {
                __nv_bfloat16* C = (__nv_bfloat16*)Cv;
                if (r0 < M)
                    *(__nv_bfloat162*)(C + (size_t)r0 * N + gn) =
                        __nv_bfloat162(__float2bfloat16(x0), __float2bfloat16(x1));
                if (r0 + 8 < M)
                    *(__nv_bfloat162*)(C + (size_t)(r0 + 8) * N + gn) =
                        __nv_bfloat162(__float2bfloat16(x2), __float2bfloat16(x3));
            } else {
                float* C = (float*)Cv;
                if (r0 < M)     *(float2*)(C + (size_t)r0 * N + gn)       = make_float2(x0, x1);
                if (r0 + 8 < M) *(float2*)(C + (size_t)(r0 + 8) * N + gn) = make_float2(x2, x3);
            }
        }
    }
}

// ---------------------------------------------------------------------------
// Gather + elementwise product + concat into F0[B, 1024] (bf16) -- R11.
// ---------------------------------------------------------------------------
__global__ __launch_bounds__(256) void build_factor(
    const int* __restrict__ rows, const int* __restrict__ cols,
    const float* __restrict__ uix, const float* __restrict__ iix,
    const __nv_bfloat16* __restrict__ T, __nv_bfloat16* __restrict__ F0)
{
    const int b0 = blockIdx.x * BF_E;
    const int t  = threadIdx.x;
    const int f  = t * 4;

    int rr[BF_E], cc[BF_E];
    {
        int4 ra = *(const int4*)(rows + b0);
        int4 rb_ = *(const int4*)(rows + b0 + 4);
        int4 ca = *(const int4*)(cols + b0);
        int4 cb = *(const int4*)(cols + b0 + 4);
        rr[0] = ra.x; rr[1] = ra.y; rr[2] = ra.z; rr[3] = ra.w;
        rr[4] = rb_.x; rr[5] = rb_.y; rr[6] = rb_.z; rr[7] = rb_.w;
        cc[0] = ca.x; cc[1] = ca.y; cc[2] = ca.z; cc[3] = ca.w;
        cc[4] = cb.x; cc[5] = cb.y; cc[6] = cb.z; cc[7] = cb.w;
    }

    if (f < 32) {
        float4 v[BF_E];
#pragma unroll
        for (int e = 0; e < BF_E; e++)
            v[e] = *(const float4*)(uix + (size_t)rr[e] * DIMS + f);
#pragma unroll
        for (int e = 0; e < BF_E; e++) {
            __nv_bfloat16* o = F0 + (size_t)(b0 + e) * 1024 + f;
            *(__nv_bfloat162*)(o)     = __nv_bfloat162(__float2bfloat16(v[e].x), __float2bfloat16(v[e].y));
            *(__nv_bfloat162*)(o + 2) = __nv_bfloat162(__float2bfloat16(v[e].z), __float2bfloat16(v[e].w));
        }
    } else if (f < 64) {
        float4 v[BF_E];
#pragma unroll
        for (int e = 0; e < BF_E; e++)
            v[e] = *(const float4*)(iix + (size_t)cc[e] * DIMS + (f - 32));
#pragma unroll
        for (int e = 0; e < BF_E; e++) {
            __nv_bfloat16* o = F0 + (size_t)(b0 + e) * 1024 + f;
            *(__nv_bfloat162*)(o)     = __nv_bfloat162(__float2bfloat16(v[e].x), __float2bfloat16(v[e].y));
            *(__nv_bfloat162*)(o + 2) = __nv_bfloat162(__float2bfloat16(v[e].z), __float2bfloat16(v[e].w));
        }
    } else {
        uint2 av[BF_E], bv[BF_E];
#pragma unroll
        for (int e = 0; e < BF_E; e++)
            av[e] = __ldg((const uint2*)(T + (size_t)rr[e] * DIMC + (f - 64)));
#pragma unroll
        for (int e = 0; e < BF_E; e++)
            bv[e] = __ldg((const uint2*)(T + (size_t)(NUSERS + cc[e]) * DIMC + (f - 64)));
#pragma unroll
        for (int e = 0; e < BF_E; e++) {
            __nv_bfloat162 a0 = *(__nv_bfloat162*)&av[e].x;
            __nv_bfloat162 a1 = *(__nv_bfloat162*)&av[e].y;
            __nv_bfloat162 b0_ = *(__nv_bfloat162*)&bv[e].x;
            __nv_bfloat162 b1_ = *(__nv_bfloat162*)&bv[e].y;
            __nv_bfloat162 p0 = __hmul2(a0, b0_);
            __nv_bfloat162 p1 = __hmul2(a1, b1_);
            uint2 w;
            w.x = *(uint32_t*)&p0;
            w.y = *(uint32_t*)&p1;
            *(uint2*)(F0 + (size_t)(b0 + e) * 1024 + f) = w;
        }
    }
}

// ---------------------------------------------------------------------------
extern "C" void kernel_launch(void* const* d_in, const int* in_sizes, int n_in,
                              void* d_out, int out_size)
{
    const int*   rows       = (const int*)d_in[0];
    const int*   cols       = (const int*)d_in[1];
    const float* user_inter = (const float*)d_in[2];
    const float* item_inter = (const float*)d_in[3];
    const float* uix        = (const float*)d_in[4];
    const float* iix        = (const float*)d_in[5];
    const float* Wt         = (const float*)d_in[6];
    const float* bt         = (const float*)d_in[7];
    const float* W1         = (const float*)d_in[8];
    const float* b1         = (const float*)d_in[9];
    const float* W2         = (const float*)d_in[10];
    const float* b2         = (const float*)d_in[11];
    const float* W3         = (const float*)d_in[12];
    const float* b3         = (const float*)d_in[13];
    const float* Wr         = (const float*)d_in[14];
    const float* br         = (const float*)d_in[15];
    float*       out        = (float*)d_out;

    __nv_bfloat16 *Eb, *Wtb, *T, *W1b, *W2b, *W3b, *F0, *F1, *F2;
    cudaGetSymbolAddress((void**)&Eb,  g_Eb);
    cudaGetSymbolAddress((void**)&Wtb, g_Wtb);
    cudaGetSymbolAddress((void**)&T,   g_T);
    cudaGetSymbolAddress((void**)&W1b, g_W1b);
    cudaGetSymbolAddress((void**)&W2b, g_W2b);
    cudaGetSymbolAddress((void**)&W3b, g_W3b);
    cudaGetSymbolAddress((void**)&F0,  g_F0);
    cudaGetSymbolAddress((void**)&F1,  g_F1);
    cudaGetSymbolAddress((void**)&F2,  g_F2);

    static cudaStream_t s1 = nullptr;
    static cudaEvent_t evFork, evM, evL, evT, evB;
    if (!s1) {
        cudaStreamCreateWithFlags(&s1, cudaStreamNonBlocking);
        cudaEventCreateWithFlags(&evFork, cudaEventDisableTiming);
        cudaEventCreateWithFlags(&evM,    cudaEventDisableTiming);
        cudaEventCreateWithFlags(&evL,    cudaEventDisableTiming);
        cudaEventCreateWithFlags(&evT,    cudaEventDisableTiming);
        cudaEventCreateWithFlags(&evB,    cudaEventDisableTiming);
    }

    const int SZ = 3072 + 1024 + 3 * 32768;   // 102400
    cudaFuncSetAttribute(gemm_tr, cudaFuncAttributeMaxDynamicSharedMemorySize, SZ);
    cudaFuncSetAttribute(gemm_bf<true, true, false>,  cudaFuncAttributeMaxDynamicSharedMemorySize, SZ);
    cudaFuncSetAttribute(gemm_bf<true, false, true>,  cudaFuncAttributeMaxDynamicSharedMemorySize, SZ);

    const dim3 blk(256);
    cudaStream_t s0 = 0;

    // ---- fork ----
    cudaEventRecord(evFork, s0);
    cudaStreamWaitEvent(s1, evFork, 0);

    // s1: weight conversions (independent of embeddings)
    conv_w<<<1572, blk, 0, s1>>>(Wt, W1, W2, W3, Wtb, W1b, W2b, W3b);

    // s0: zero + mark
    zero_aux<<<37, blk, 0, s0>>>();
    mark_used<<<NB / 512, blk, 0, s0>>>(rows, cols);
    cudaEventRecord(evM, s0);

    // s1: build_list (needs mark)
    cudaStreamWaitEvent(s1, evM, 0);
    build_list<<<(NEMB + 255) / 256, blk, 0, s1>>>();
    cudaEventRecord(evL, s1);

    // s0: embedding conversion (needs mark; overlaps build_list/conv_w)
    conv_emb<<<NEMB / 2, blk, 0, s0>>>(user_inter, item_inter, Eb);

    // s0: transfer GEMM (needs list + Eb + Wtb)
    cudaStreamWaitEvent(s0, evL, 0);
    gemm_tr<<<dim3(8, (NEMB + 127) / 128), blk, SZ, s0>>>(Eb, Wtb, bt, T);
    cudaEventRecord(evT, s0);

    // ---- two batch-half chains: h0 on s0, h1 on s1 ----
    build_factor<<<NBH / BF_E, blk, 0, s0>>>(rows, cols, uix, iix, T, F0);
    gemm_bf<true, true, false><<<dim3(4, NBH / 128), blk, SZ, s0>>>(
        F0, W1b, b1, F1, nullptr, nullptr, NBH, 512, 1024);
    gemm_bf<true, true, false><<<dim3(2, NBH / 128), blk, SZ, s0>>>(
        F1, W2b, b2, F2, nullptr, nullptr, NBH, 256, 512);
    gemm_bf<true, false, true><<<dim3(1, NBH / 128), blk, SZ, s0>>>(
        F2, W3b, b3, out, Wr, br, NBH, 128, 256);

    cudaStreamWaitEvent(s1, evT, 0);
    build_factor<<<NBH / BF_E, blk, 0, s1>>>(
        rows + NBH, cols + NBH, uix, iix, T, F0 + (size_t)NBH * 1024);
    gemm_bf<true, true, false><<<dim3(4, NBH / 128), blk, SZ, s1>>>(
        F0 + (size_t)NBH * 1024, W1b, b1, F1 + (size_t)NBH * 512,
        nullptr, nullptr, NBH, 512, 1024);
    gemm_bf<true, true, false><<<dim3(2, NBH / 128), blk, SZ, s1>>>(
        F1 + (size_t)NBH * 512, W2b, b2, F2 + (size_t)NBH * 256,
        nullptr, nullptr, NBH, 256, 512);
    gemm_bf<true, false, true><<<dim3(1, NBH / 128), blk, SZ, s1>>>(
        F2 + (size_t)NBH * 256, W3b, b3, out + NBH, Wr, br, NBH, 128, 256);
    cudaEventRecord(evB, s1);

    // ---- join ----
    cudaStreamWaitEvent(s0, evB, 0);
}

// round 16
// speedup vs baseline: 1.0082x; 1.0001x over previous
#include <cuda_runtime.h>
#include <cuda_bf16.h>
#include <cstdint>
#include <cstddef>

// ===========================================================================
// DaConA on GB300 (sm_103 PTX target: mma.sync bf16 HMMA k16 + ldmatrix with
// hoisted swizzle addressing).  Converged configuration:
//  - per-entity transfer GEMM over batch-referenced rows only (compact list)
//  - bf16 everywhere (fp32 accum), rel_err ~3.7e-6 (270x under threshold)
//  - dual-stream fork-join: conv_w/build_list on side stream; MLP split in
//    two batch halves across streams; final Wr-dot fused into last GEMM
// pred = MLP(concat(u_indep[r], i_indep[c], (Wt@u[r]+bt)*(Wt@i[c]+bt))) + 3.5
// ===========================================================================

#define NB      131072
#define NUSERS  100000
#define NITEMS  50000
#define NEMB    150000
#define DIMC    960
#define DIMS    32
#define BF_E    8
#define NBH     (NB / 2)

__device__ __nv_bfloat16 g_Eb[(size_t)NEMB * DIMC];
__device__ __nv_bfloat16 g_Wtb[(size_t)DIMC * DIMC];
__device__ __nv_bfloat16 g_T [(size_t)NEMB * DIMC];
__device__ __nv_bfloat16 g_W1b[512 * 1024];
__device__ __nv_bfloat16 g_W2b[256 * 512];
__device__ __nv_bfloat16 g_W3b[128 * 256];
__device__ __nv_bfloat16 g_F0[(size_t)NB * 1024];
__device__ __nv_bfloat16 g_F1[(size_t)NB * 512];
__device__ __nv_bfloat16 g_F2[(size_t)NB * 256];
__device__ unsigned char g_used[NEMB];
__device__ int g_list[NEMB];
__device__ int g_cnt;

__device__ __forceinline__ uint32_t smem_u32(const void* p) {
    uint32_t a;
    asm("{ .reg .u64 t; cvta.to.shared.u64 t, %1; cvt.u32.u64 %0, t; }" : "=r"(a) : "l"(p));
    return a;
}
#define SWZ128(o) ((o) ^ (((o) >> 3) & 0x70))

__device__ __forceinline__ void cp16(uint32_t dst, const void* src, uint32_t sz) {
    asm volatile("cp.async.cg.shared.global [%0], [%1], 16, %2;" :: "r"(dst), "l"(src), "r"(sz));
}
__device__ __forceinline__ void ldsm4(uint32_t* r, uint32_t addr) {
    asm volatile("ldmatrix.sync.aligned.m8n8.x4.shared.b16 {%0,%1,%2,%3}, [%4];"
                 : "=r"(r[0]), "=r"(r[1]), "=r"(r[2]), "=r"(r[3]) : "r"(addr));
}
__device__ __forceinline__ void mma16(float* d, const uint32_t* a, const uint32_t* b) {
    asm volatile("mma.sync.aligned.m16n8k16.row.col.f32.bf16.bf16.f32 "
                 "{%0,%1,%2,%3}, {%4,%5,%6,%7}, {%8,%9}, {%0,%1,%2,%3};"
                 : "+f"(d[0]), "+f"(d[1]), "+f"(d[2]), "+f"(d[3])
                 : "r"(a[0]), "r"(a[1]), "r"(a[2]), "r"(a[3]), "r"(b[0]), "r"(b[1]));
}

// ---------------------------------------------------------------------------
// Aux: zero bitmap+counter; mark used entities; build compact list.
// ---------------------------------------------------------------------------
__global__ __launch_bounds__(256) void zero_aux() {
    const int i = blockIdx.x * 256 + threadIdx.x;
#pragma unroll
    for (int k = 0; k < 4; k++) {
        int j = i + k * 9472;                   // 37 blocks * 256
        if (j < NEMB / 4) ((uint32_t*)g_used)[j] = 0;
    }
    if (i == 0) g_cnt = 0;
}
__global__ __launch_bounds__(256) void mark_used(
    const int* __restrict__ rows, const int* __restrict__ cols) {
    const int i = (blockIdx.x * 256 + threadIdx.x) * 4;
    int4 r = *(const int4*)(rows + i);
    int4 c = *(const int4*)(cols + i);
    g_used[r.x] = 1; g_used[r.y] = 1; g_used[r.z] = 1; g_used[r.w] = 1;
    g_used[NUSERS + c.x] = 1; g_used[NUSERS + c.y] = 1;
    g_used[NUSERS + c.z] = 1; g_used[NUSERS + c.w] = 1;
}
__global__ __launch_bounds__(256) void build_list() {
    const int e = blockIdx.x * 256 + threadIdx.x;
    if (e < NEMB && g_used[e]) {
        int p = atomicAdd(&g_cnt, 1);
        g_list[p] = e;
    }
}

// ---------------------------------------------------------------------------
// fp32 -> bf16 embedding conversion, USED rows only.
// ---------------------------------------------------------------------------
__global__ __launch_bounds__(256) void conv_emb(
    const float* __restrict__ user_inter, const float* __restrict__ item_inter,
    __nv_bfloat16* __restrict__ Eb)
{
    const int t = threadIdx.x;
    if (t >= 240) return;
    const int r0 = blockIdx.x * 2;
    const uchar2 u = *(const uchar2*)(g_used + r0);

    const float* s0 = (r0 < NUSERS) ? user_inter + (size_t)r0 * DIMC
                                    : item_inter + (size_t)(r0 - NUSERS) * DIMC;
    const int r1 = r0 + 1;
    const float* s1 = (r1 < NUSERS) ? user_inter + (size_t)r1 * DIMC
                                    : item_inter + (size_t)(r1 - NUSERS) * DIMC;
    float4 v0, v1;
    if (u.x) v0 = *(const float4*)(s0 + t * 4);
    if (u.y) v1 = *(const float4*)(s1 + t * 4);
    if (u.x) {
        __nv_bfloat16* d = Eb + (size_t)r0 * DIMC + t * 4;
        *(__nv_bfloat162*)(d)     = __nv_bfloat162(__float2bfloat16(v0.x), __float2bfloat16(v0.y));
        *(__nv_bfloat162*)(d + 2) = __nv_bfloat162(__float2bfloat16(v0.z), __float2bfloat16(v0.w));
    }
    if (u.y) {
        __nv_bfloat16* d = Eb + (size_t)r1 * DIMC + t * 4;
        *(__nv_bfloat162*)(d)     = __nv_bfloat162(__float2bfloat16(v1.x), __float2bfloat16(v1.y));
        *(__nv_bfloat162*)(d + 2) = __nv_bfloat162(__float2bfloat16(v1.z), __float2bfloat16(v1.w));
    }
}

// ---------------------------------------------------------------------------
// Wt | W1 | W2 | W3 fp32 -> bf16
// ---------------------------------------------------------------------------
__device__ __forceinline__ void conv_blk(const float* src, __nv_bfloat16* dst, size_t blk) {
    const size_t i = blk * 1024 + threadIdx.x * 4;
    float4 v = *(const float4*)(src + i);
    *(__nv_bfloat162*)(dst + i)     = __nv_bfloat162(__float2bfloat16(v.x), __float2bfloat16(v.y));
    *(__nv_bfloat162*)(dst + i + 2) = __nv_bfloat162(__float2bfloat16(v.z), __float2bfloat16(v.w));
}
__global__ __launch_bounds__(256) void conv_w(
    const float* __restrict__ Wt, const float* __restrict__ W1,
    const float* __restrict__ W2, const float* __restrict__ W3,
    __nv_bfloat16* __restrict__ Wtb, __nv_bfloat16* __restrict__ W1b,
    __nv_bfloat16* __restrict__ W2b, __nv_bfloat16* __restrict__ W3b)
{
    const int b = blockIdx.x;
    if      (b < 900)  conv_blk(Wt, Wtb, b);
    else if (b < 1412) conv_blk(W1, W1b, b - 900);
    else if (b < 1540) conv_blk(W2, W2b, b - 1412);
    else               conv_blk(W3, W3b, b - 1540);
}

// ---------------------------------------------------------------------------
// Transfer GEMM over COMPACTED rows.
// ---------------------------------------------------------------------------
__global__ __launch_bounds__(256) void gemm_tr(
    const __nv_bfloat16* __restrict__ Eb, const __nv_bfloat16* __restrict__ Bw,
    const float* __restrict__ bias, __nv_bfloat16* __restrict__ T)
{
    const int cnt = g_cnt;
    const int bm = blockIdx.y * 128;
    if (bm >= cnt) return;
    const int bn = blockIdx.x * 128;

    extern __shared__ char smem[];
    const uint32_t base = smem_u32(smem);
    const int t = threadIdx.x;
    const int wid = t >> 5, lane = t & 31;
    const int wm = wid >> 2, wn = wid & 3;
    const int g = lane >> 2, q = lane & 3;

    constexpr int TILE = 16384;
    constexpr int SB   = 2 * TILE;

    float* biass = (float*)(smem);
    int*   idxs  = (int*)(smem + 1024);
    const uint32_t tiles = (base + 3072 + 1023) & ~1023u;

    for (int j = t; j < 128; j += 256) {
        int gn = bn + j;
        biass[j] = (gn < DIMC) ? bias[gn] : 0.f;
        idxs[j]  = (bm + j < cnt) ? __ldg(g_list + bm + j) : 0;
    }

    const int seg = t & 7;
    const int rb  = t >> 3;

    int aidx[4]; uint32_t aok[4];
#pragma unroll
    for (int rr = 0; rr < 4; rr++) {
        int gr = bm + rb + rr * 32;
        aok[rr]  = (gr < cnt) ? 16u : 0u;
        aidx[rr] = (gr < cnt) ? __ldg(g_list + gr) : 0;
    }

    auto load_chunk = [&](int c, int s) {
        const uint32_t at = tiles + s * SB;
        const uint32_t bt_ = at + TILE;
#pragma unroll
        for (int rr = 0; rr < 4; rr++) {
            int row = rb + rr * 32;
            const __nv_bfloat16* src = Eb + (size_t)aidx[rr] * DIMC + c * 64 + seg * 8;
            cp16(at + SWZ128(row * 128 + seg * 16), src, aok[rr]);
        }
#pragma unroll
        for (int rr = 0; rr < 4; rr++) {
            int row = rb + rr * 32;
            int gn  = bn + row;
            int ok  = gn < DIMC;
            const __nv_bfloat16* src = Bw + (size_t)(ok ? gn : 0) * DIMC + c * 64 + seg * 8;
            cp16(bt_ + SWZ128(row * 128 + seg * 16), src, ok ? 16u : 0u);
        }
        asm volatile("cp.async.commit_group;" ::: "memory");
    };

    float acc[4][4][4];
#pragma unroll
    for (int i = 0; i < 4; i++)
#pragma unroll
        for (int j = 0; j < 4; j++)
#pragma unroll
            for (int v = 0; v < 4; v++) acc[i][j][v] = 0.f;

    const int arow = lane & 15;
    const int aoff = (lane >> 4) * 16;
    const int axor = (arow & 7) << 4;
    const int bm8  = lane >> 3;
    const int brow = ((bm8 >> 1) << 3) + (lane & 7);
    const int boff = (bm8 & 1) * 16;
    const int bxor = (lane & 7) << 4;
    uint32_t off_a[4], off_b[4];
#pragma unroll
    for (int ks = 0; ks < 4; ks++) {
        off_a[ks] = (uint32_t)((wm * 64 + arow) * 128 + ((ks * 32 + aoff) ^ axor));
        off_b[ks] = (uint32_t)((wn * 32 + brow) * 128 + ((ks * 32 + boff) ^ bxor)) + TILE;
    }

    const int NKc = DIMC >> 6;
    load_chunk(0, 0);
    load_chunk(1, 1);

    for (int i = 0; i < NKc; i++) {
        const int s = i - (i / 3) * 3;
        if (i + 1 < NKc) asm volatile("cp.async.wait_group 1;" ::: "memory");
        else             asm volatile("cp.async.wait_group 0;" ::: "memory");
        __syncthreads();
        if (i + 2 < NKc) {
            int s2 = i + 2; s2 -= (s2 / 3) * 3;
            load_chunk(i + 2, s2);
        }

        const uint32_t st = tiles + s * SB;
#pragma unroll
        for (int ks = 0; ks < 4; ks++) {
            uint32_t af[4][4], bf[4][2];
            const uint32_t ab = st + off_a[ks];
            const uint32_t bb = st + off_b[ks];
#pragma unroll
            for (int mt = 0; mt < 4; mt++)
                ldsm4(af[mt], ab + mt * 2048);
#pragma unroll
            for (int np = 0; np < 2; np++) {
                uint32_t r[4];
                ldsm4(r, bb + np * 2048);
                bf[2 * np][0] = r[0]; bf[2 * np][1] = r[1];
                bf[2 * np + 1][0] = r[2]; bf[2 * np + 1][1] = r[3];
            }
#pragma unroll
            for (int mt = 0; mt < 4; mt++)
#pragma unroll
                for (int nt = 0; nt < 4; nt++)
                    mma16(acc[mt][nt], af[mt], bf[nt]);
        }
    }
    __syncthreads();

#pragma unroll
    for (int mt = 0; mt < 4; mt++) {
        const int er0 = wm * 64 + mt * 16 + g;
#pragma unroll
        for (int nt = 0; nt < 4; nt++) {
            const int jc = wn * 32 + nt * 8 + 2 * q;
            const int gn = bn + jc;
            if (gn >= DIMC) continue;
            const float bx = biass[jc], by = biass[jc + 1];
            float x0 = acc[mt][nt][0] + bx, x1 = acc[mt][nt][1] + by;
            float x2 = acc[mt][nt][2] + bx, x3 = acc[mt][nt][3] + by;
            if (bm + er0 < cnt)
                *(__nv_bfloat162*)(T + (size_t)idxs[er0] * DIMC + gn) =
                    __nv_bfloat162(__float2bfloat16(x0), __float2bfloat16(x1));
            if (bm + er0 + 8 < cnt)
                *(__nv_bfloat162*)(T + (size_t)idxs[er0 + 8] * DIMC + gn) =
                    __nv_bfloat162(__float2bfloat16(x2), __float2bfloat16(x3));
        }
    }
}

// ---------------------------------------------------------------------------
// bf16 mma.sync NT GEMM: BM=BN=128, 3-stage cp.async, ldmatrix hoisted.
// FINAL fuses out[b] = tanh(row).Wr + br + 3.5 (N==128).
// ---------------------------------------------------------------------------
template<bool TANH, bool OUT_BF16, bool FINAL>
__global__ __launch_bounds__(256) void gemm_bf(
    const __nv_bfloat16* __restrict__ A, const __nv_bfloat16* __restrict__ Bw,
    const float* __restrict__ bias, void* __restrict__ Cv,
    const float* __restrict__ Wr, const float* __restrict__ brp,
    int M, int N, int K)
{
    extern __shared__ char smem[];
    const uint32_t base = smem_u32(smem);
    const int t = threadIdx.x;
    const int wid = t >> 5, lane = t & 31;
    const int wm = wid >> 2, wn = wid & 3;
    const int g = lane >> 2, q = lane & 3;

    constexpr int TILE = 16384;
    constexpr int SB   = 2 * TILE;
    const int bm = blockIdx.y * 128;
    const int bn = blockIdx.x * 128;

    float* biass = (float*)(smem);
    float* wrs   = (float*)(smem + 512);
    float* part  = (float*)(smem + 1024);
    const uint32_t tiles = (base + 3072 + 1023) & ~1023u;

    for (int j = t; j < 128; j += 256) {
        int gn = bn + j;
        biass[j] = (gn < N) ? bias[gn] : 0.f;
        if (FINAL) wrs[j] = Wr[j];
    }

    const int seg = t & 7;
    const int rb  = t >> 3;

    auto load_chunk = [&](int c, int s) {
        const uint32_t at = tiles + s * SB;
        const uint32_t bt_ = at + TILE;
#pragma unroll
        for (int rr = 0; rr < 4; rr++) {
            int row = rb + rr * 32;
            int gr  = bm + row;
            int ok  = gr < M;
            const __nv_bfloat16* src = A + (size_t)(ok ? gr : 0) * K + c * 64 + seg * 8;
            cp16(at + SWZ128(row * 128 + seg * 16), src, ok ? 16u : 0u);
        }
#pragma unroll
        for (int rr = 0; rr < 4; rr++) {
            int row = rb + rr * 32;
            int gn  = bn + row;
            int ok  = gn < N;
            const __nv_bfloat16* src = Bw + (size_t)(ok ? gn : 0) * K + c * 64 + seg * 8;
            cp16(bt_ + SWZ128(row * 128 + seg * 16), src, ok ? 16u : 0u);
        }
        asm volatile("cp.async.commit_group;" ::: "memory");
    };

    float acc[4][4][4];
#pragma unroll
    for (int i = 0; i < 4; i++)
#pragma unroll
        for (int j = 0; j < 4; j++)
#pragma unroll
            for (int v = 0; v < 4; v++) acc[i][j][v] = 0.f;

    const int arow = lane & 15;
    const int aoff = (lane >> 4) * 16;
    const int axor = (arow & 7) << 4;
    const int bm8  = lane >> 3;
    const int brow = ((bm8 >> 1) << 3) + (lane & 7);
    const int boff = (bm8 & 1) * 16;
    const int bxor = (lane & 7) << 4;
    uint32_t off_a[4], off_b[4];
#pragma unroll
    for (int ks = 0; ks < 4; ks++) {
        off_a[ks] = (uint32_t)((wm * 64 + arow) * 128 + ((ks * 32 + aoff) ^ axor));
        off_b[ks] = (uint32_t)((wn * 32 + brow) * 128 + ((ks * 32 + boff) ^ bxor)) + TILE;
    }

    const int NKc = K >> 6;
    load_chunk(0, 0);
    load_chunk(1, 1);

    for (int i = 0; i < NKc; i++) {
        const int s = i - (i / 3) * 3;
        if (i + 1 < NKc) asm volatile("cp.async.wait_group 1;" ::: "memory");
        else             asm volatile("cp.async.wait_group 0;" ::: "memory");
        __syncthreads();
        if (i + 2 < NKc) {
            int s2 = i + 2; s2 -= (s2 / 3) * 3;
            load_chunk(i + 2, s2);
        }

        const uint32_t st = tiles + s * SB;
#pragma unroll
        for (int ks = 0; ks < 4; ks++) {
            uint32_t af[4][4], bf[4][2];
            const uint32_t ab = st + off_a[ks];
            const uint32_t bb = st + off_b[ks];
#pragma unroll
            for (int mt = 0; mt < 4; mt++)
                ldsm4(af[mt], ab + mt * 2048);
#pragma unroll
            for (int np = 0; np < 2; np++) {
                uint32_t r[4];
                ldsm4(r, bb + np * 2048);
                bf[2 * np][0] = r[0]; bf[2 * np][1] = r[1];
                bf[2 * np + 1][0] = r[2]; bf[2 * np + 1][1] = r[3];
            }
#pragma unroll
            for (int mt = 0; mt < 4; mt++)
#pragma unroll
                for (int nt = 0; nt < 4; nt++)
                    mma16(acc[mt][nt], af[mt], bf[nt]);
        }
    }
    __syncthreads();

    if (FINAL) {
#pragma unroll
        for (int mt = 0; mt < 4; mt++) {
            float p0 = 0.f, p1 = 0.f;
#pragma unroll
            for (int nt = 0; nt < 4; nt++) {
                const int jc = wn * 32 + nt * 8 + 2 * q;
                const float bx = biass[jc], by = biass[jc + 1];
                const float wx = wrs[jc],  wy = wrs[jc + 1];
                p0 += tanhf(acc[mt][nt][0] + bx) * wx + tanhf(acc[mt][nt][1] + by) * wy;
                p1 += tanhf(acc[mt][nt][2] + bx) * wx + tanhf(acc[mt][nt][3] + by) * wy;
            }
            p0 += __shfl_xor_sync(0xFFFFFFFFu, p0, 1);
            p0 += __shfl_xor_sync(0xFFFFFFFFu, p0, 2);
            p1 += __shfl_xor_sync(0xFFFFFFFFu, p1, 1);
            p1 += __shfl_xor_sync(0xFFFFFFFFu, p1, 2);
            if (q == 0) {
                part[(wm * 64 + mt * 16 + g) * 4 + wn]     = p0;
                part[(wm * 64 + mt * 16 + g + 8) * 4 + wn] = p1;
            }
        }
        __syncthreads();
        if (t < 128) {
            float s = part[t * 4] + part[t * 4 + 1] + part[t * 4 + 2] + part[t * 4 + 3];
            if (bm + t < M) ((float*)Cv)[bm + t] = s + brp[0] + 3.5f;
        }
        return;
    }

#pragma unroll
    for (int mt = 0; mt < 4; mt++) {
        const int r0 = bm + wm * 64 + mt * 16 + g;
#pragma unroll
        for (int nt = 0; nt < 4; nt++) {
            const int jc = wn * 32 + nt * 8 + 2 * q;
            const int gn = bn + jc;
            if (gn >= N) continue;
            const float bx = biass[jc], by = biass[jc + 1];
            float x0 = acc[mt][nt][0] + bx, x1 = acc[mt][nt][1] + by;
            float x2 = acc[mt][nt][2] + bx, x3 = acc[mt][nt][3] + by;
            if (TANH) { x0 = tanhf(x0); x1 = tanhf(x1); x2 = tanhf(x2); x3 = tanhf(x3); }
            if (OUT_BF16) {
                __nv_bfloat16* C = (__nv_bfloat16*)Cv;
                if (r0 < M)
                    *(__nv_bfloat162*)(C + (size_t)r0 * N + gn) =
                        __nv_bfloat162(__float2bfloat16(x0), __float2bfloat16(x1));
                if (r0 + 8 < M)
                    *(__nv_bfloat162*)(C + (size_t)(r0 + 8) * N + gn) =
                        __nv_bfloat162(__float2bfloat16(x2), __float2bfloat16(x3));
            } else {
                float* C = (float*)Cv;
                if (r0 < M)     *(float2*)(C + (size_t)r0 * N + gn)       = make_float2(x0, x1);
                if (r0 + 8 < M) *(float2*)(C + (size_t)(r0 + 8) * N + gn) = make_float2(x2, x3);
            }
        }
    }
}

// ---------------------------------------------------------------------------
// Gather + elementwise product + concat into F0[B, 1024] (bf16).
// ---------------------------------------------------------------------------
__global__ __launch_bounds__(256) void build_factor(
    const int* __restrict__ rows, const int* __restrict__ cols,
    const float* __restrict__ uix, const float* __restrict__ iix,
    const __nv_bfloat16* __restrict__ T, __nv_bfloat16* __restrict__ F0)
{
    const int b0 = blockIdx.x * BF_E;
    const int t  = threadIdx.x;
    const int f  = t * 4;

    int rr[BF_E], cc[BF_E];
    {
        int4 ra = *(const int4*)(rows + b0);
        int4 rb_ = *(const int4*)(rows + b0 + 4);
        int4 ca = *(const int4*)(cols + b0);
        int4 cb = *(const int4*)(cols + b0 + 4);
        rr[0] = ra.x; rr[1] = ra.y; rr[2] = ra.z; rr[3] = ra.w;
        rr[4] = rb_.x; rr[5] = rb_.y; rr[6] = rb_.z; rr[7] = rb_.w;
        cc[0] = ca.x; cc[1] = ca.y; cc[2] = ca.z; cc[3] = ca.w;
        cc[4] = cb.x; cc[5] = cb.y; cc[6] = cb.z; cc[7] = cb.w;
    }

    if (f < 32) {
        float4 v[BF_E];
#pragma unroll
        for (int e = 0; e < BF_E; e++)
            v[e] = *(const float4*)(uix + (size_t)rr[e] * DIMS + f);
#pragma unroll
        for (int e = 0; e < BF_E; e++) {
            __nv_bfloat16* o = F0 + (size_t)(b0 + e) * 1024 + f;
            *(__nv_bfloat162*)(o)     = __nv_bfloat162(__float2bfloat16(v[e].x), __float2bfloat16(v[e].y));
            *(__nv_bfloat162*)(o + 2) = __nv_bfloat162(__float2bfloat16(v[e].z), __float2bfloat16(v[e].w));
        }
    } else if (f < 64) {
        float4 v[BF_E];
#pragma unroll
        for (int e = 0; e < BF_E; e++)
            v[e] = *(const float4*)(iix + (size_t)cc[e] * DIMS + (f - 32));
#pragma unroll
        for (int e = 0; e < BF_E; e++) {
            __nv_bfloat16* o = F0 + (size_t)(b0 + e) * 1024 + f;
            *(__nv_bfloat162*)(o)     = __nv_bfloat162(__float2bfloat16(v[e].x), __float2bfloat16(v[e].y));
            *(__nv_bfloat162*)(o + 2) = __nv_bfloat162(__float2bfloat16(v[e].z), __float2bfloat16(v[e].w));
        }
    } else {
        uint2 av[BF_E], bv[BF_E];
#pragma unroll
        for (int e = 0; e < BF_E; e++)
            av[e] = __ldg((const uint2*)(T + (size_t)rr[e] * DIMC + (f - 64)));
#pragma unroll
        for (int e = 0; e < BF_E; e++)
            bv[e] = __ldg((const uint2*)(T + (size_t)(NUSERS + cc[e]) * DIMC + (f - 64)));
#pragma unroll
        for (int e = 0; e < BF_E; e++) {
            __nv_bfloat162 a0 = *(__nv_bfloat162*)&av[e].x;
            __nv_bfloat162 a1 = *(__nv_bfloat162*)&av[e].y;
            __nv_bfloat162 b0_ = *(__nv_bfloat162*)&bv[e].x;
            __nv_bfloat162 b1_ = *(__nv_bfloat162*)&bv[e].y;
            __nv_bfloat162 p0 = __hmul2(a0, b0_);
            __nv_bfloat162 p1 = __hmul2(a1, b1_);
            uint2 w;
            w.x = *(uint32_t*)&p0;
            w.y = *(uint32_t*)&p1;
            *(uint2*)(F0 + (size_t)(b0 + e) * 1024 + f) = w;
        }
    }
}

// ---------------------------------------------------------------------------
extern "C" void kernel_launch(void* const* d_in, const int* in_sizes, int n_in,
                              void* d_out, int out_size)
{
    const int*   rows       = (const int*)d_in[0];
    const int*   cols       = (const int*)d_in[1];
    const float* user_inter = (const float*)d_in[2];
    const float* item_inter = (const float*)d_in[3];
    const float* uix        = (const float*)d_in[4];
    const float* iix        = (const float*)d_in[5];
    const float* Wt         = (const float*)d_in[6];
    const float* bt         = (const float*)d_in[7];
    const float* W1         = (const float*)d_in[8];
    const float* b1         = (const float*)d_in[9];
    const float* W2         = (const float*)d_in[10];
    const float* b2         = (const float*)d_in[11];
    const float* W3         = (const float*)d_in[12];
    const float* b3         = (const float*)d_in[13];
    const float* Wr         = (const float*)d_in[14];
    const float* br         = (const float*)d_in[15];
    float*       out        = (float*)d_out;

    __nv_bfloat16 *Eb, *Wtb, *T, *W1b, *W2b, *W3b, *F0, *F1, *F2;
    cudaGetSymbolAddress((void**)&Eb,  g_Eb);
    cudaGetSymbolAddress((void**)&Wtb, g_Wtb);
    cudaGetSymbolAddress((void**)&T,   g_T);
    cudaGetSymbolAddress((void**)&W1b, g_W1b);
    cudaGetSymbolAddress((void**)&W2b, g_W2b);
    cudaGetSymbolAddress((void**)&W3b, g_W3b);
    cudaGetSymbolAddress((void**)&F0,  g_F0);
    cudaGetSymbolAddress((void**)&F1,  g_F1);
    cudaGetSymbolAddress((void**)&F2,  g_F2);

    static cudaStream_t s1 = nullptr;
    static cudaEvent_t evFork, evM, evL, evT, evB;
    if (!s1) {
        cudaStreamCreateWithFlags(&s1, cudaStreamNonBlocking);
        cudaEventCreateWithFlags(&evFork, cudaEventDisableTiming);
        cudaEventCreateWithFlags(&evM,    cudaEventDisableTiming);
        cudaEventCreateWithFlags(&evL,    cudaEventDisableTiming);
        cudaEventCreateWithFlags(&evT,    cudaEventDisableTiming);
        cudaEventCreateWithFlags(&evB,    cudaEventDisableTiming);
    }

    const int SZ = 3072 + 1024 + 3 * 32768;   // 102400
    cudaFuncSetAttribute(gemm_tr, cudaFuncAttributeMaxDynamicSharedMemorySize, SZ);
    cudaFuncSetAttribute(gemm_bf<true, true, false>,  cudaFuncAttributeMaxDynamicSharedMemorySize, SZ);
    cudaFuncSetAttribute(gemm_bf<true, false, true>,  cudaFuncAttributeMaxDynamicSharedMemorySize, SZ);

    const dim3 blk(256);
    cudaStream_t s0 = 0;

    // ---- fork ----
    cudaEventRecord(evFork, s0);
    cudaStreamWaitEvent(s1, evFork, 0);

    // s1: weight conversions (independent of embeddings)
    conv_w<<<1572, blk, 0, s1>>>(Wt, W1, W2, W3, Wtb, W1b, W2b, W3b);

    // s0: zero + mark
    zero_aux<<<37, blk, 0, s0>>>();
    mark_used<<<NB / 1024, blk, 0, s0>>>(rows, cols);
    cudaEventRecord(evM, s0);

    // s1: build_list (needs mark)
    cudaStreamWaitEvent(s1, evM, 0);
    build_list<<<(NEMB + 255) / 256, blk, 0, s1>>>();
    cudaEventRecord(evL, s1);

    // s0: embedding conversion (needs mark; overlaps build_list/conv_w)
    conv_emb<<<NEMB / 2, blk, 0, s0>>>(user_inter, item_inter, Eb);

    // s0: transfer GEMM (needs list + Eb + Wtb)
    cudaStreamWaitEvent(s0, evL, 0);
    gemm_tr<<<dim3(8, (NEMB + 127) / 128), blk, SZ, s0>>>(Eb, Wtb, bt, T);
    cudaEventRecord(evT, s0);

    // ---- two batch-half chains: h0 on s0, h1 on s1 ----
    build_factor<<<NBH / BF_E, blk, 0, s0>>>(rows, cols, uix, iix, T, F0);
    gemm_bf<true, true, false><<<dim3(4, NBH / 128), blk, SZ, s0>>>(
        F0, W1b, b1, F1, nullptr, nullptr, NBH, 512, 1024);
    gemm_bf<true, true, false><<<dim3(2, NBH / 128), blk, SZ, s0>>>(
        F1, W2b, b2, F2, nullptr, nullptr, NBH, 256, 512);
    gemm_bf<true, false, true><<<dim3(1, NBH / 128), blk, SZ, s0>>>(
        F2, W3b, b3, out, Wr, br, NBH, 128, 256);

    cudaStreamWaitEvent(s1, evT, 0);
    build_factor<<<NBH / BF_E, blk, 0, s1>>>(
        rows + NBH, cols + NBH, uix, iix, T, F0 + (size_t)NBH * 1024);
    gemm_bf<true, true, false><<<dim3(4, NBH / 128), blk, SZ, s1>>>(
        F0 + (size_t)NBH * 1024, W1b, b1, F1 + (size_t)NBH * 512,
        nullptr, nullptr, NBH, 512, 1024);
    gemm_bf<true, true, false><<<dim3(2, NBH / 128), blk, SZ, s1>>>(
        F1 + (size_t)NBH * 512, W2b, b2, F2 + (size_t)NBH * 256,
        nullptr, nullptr, NBH, 256, 512);
    gemm_bf<true, false, true><<<dim3(1, NBH / 128), blk, SZ, s1>>>(
        F2 + (size_t)NBH * 256, W3b, b3, out + NBH, Wr, br, NBH, 128, 256);
    cudaEventRecord(evB, s1);

    // ---- join ----
    cudaStreamWaitEvent(s0, evB, 0);
}

// round 17
// speedup vs baseline: 1.0232x; 1.0149x over previous
#include <cuda_runtime.h>
#include <cuda_bf16.h>
#include <cstdint>
#include <cstddef>

// ===========================================================================
// DaConA on GB300 (sm_103 PTX target: mma.sync bf16 HMMA k16 + ldmatrix with
// hoisted swizzle addressing).
// R17: transfer GEMM exact-N tiling -- cols 0..895 in 7 full 128-col blocks,
// cols 896..959 in a half-cost 64-col tail kernel on the side stream.
// pred = MLP(concat(u_indep[r], i_indep[c], (Wt@u[r]+bt)*(Wt@i[c]+bt))) + 3.5
// ===========================================================================

#define NB      131072
#define NUSERS  100000
#define NITEMS  50000
#define NEMB    150000
#define DIMC    960
#define DIMS    32
#define BF_E    8
#define NBH     (NB / 2)

__device__ __nv_bfloat16 g_Eb[(size_t)NEMB * DIMC];
__device__ __nv_bfloat16 g_Wtb[(size_t)DIMC * DIMC];
__device__ __nv_bfloat16 g_T [(size_t)NEMB * DIMC];
__device__ __nv_bfloat16 g_W1b[512 * 1024];
__device__ __nv_bfloat16 g_W2b[256 * 512];
__device__ __nv_bfloat16 g_W3b[128 * 256];
__device__ __nv_bfloat16 g_F0[(size_t)NB * 1024];
__device__ __nv_bfloat16 g_F1[(size_t)NB * 512];
__device__ __nv_bfloat16 g_F2[(size_t)NB * 256];
__device__ unsigned char g_used[NEMB];
__device__ int g_list[NEMB];
__device__ int g_cnt;

__device__ __forceinline__ uint32_t smem_u32(const void* p) {
    uint32_t a;
    asm("{ .reg .u64 t; cvta.to.shared.u64 t, %1; cvt.u32.u64 %0, t; }" : "=r"(a) : "l"(p));
    return a;
}
#define SWZ128(o) ((o) ^ (((o) >> 3) & 0x70))

__device__ __forceinline__ void cp16(uint32_t dst, const void* src, uint32_t sz) {
    asm volatile("cp.async.cg.shared.global [%0], [%1], 16, %2;" :: "r"(dst), "l"(src), "r"(sz));
}
__device__ __forceinline__ void ldsm4(uint32_t* r, uint32_t addr) {
    asm volatile("ldmatrix.sync.aligned.m8n8.x4.shared.b16 {%0,%1,%2,%3}, [%4];"
                 : "=r"(r[0]), "=r"(r[1]), "=r"(r[2]), "=r"(r[3]) : "r"(addr));
}
__device__ __forceinline__ void mma16(float* d, const uint32_t* a, const uint32_t* b) {
    asm volatile("mma.sync.aligned.m16n8k16.row.col.f32.bf16.bf16.f32 "
                 "{%0,%1,%2,%3}, {%4,%5,%6,%7}, {%8,%9}, {%0,%1,%2,%3};"
                 : "+f"(d[0]), "+f"(d[1]), "+f"(d[2]), "+f"(d[3])
                 : "r"(a[0]), "r"(a[1]), "r"(a[2]), "r"(a[3]), "r"(b[0]), "r"(b[1]));
}

// ---------------------------------------------------------------------------
// Aux: zero bitmap+counter; mark used entities; build compact list.
// ---------------------------------------------------------------------------
__global__ __launch_bounds__(256) void zero_aux() {
    const int i = blockIdx.x * 256 + threadIdx.x;
#pragma unroll
    for (int k = 0; k < 4; k++) {
        int j = i + k * 9472;
        if (j < NEMB / 4) ((uint32_t*)g_used)[j] = 0;
    }
    if (i == 0) g_cnt = 0;
}
__global__ __launch_bounds__(256) void mark_used(
    const int* __restrict__ rows, const int* __restrict__ cols) {
    const int i = (blockIdx.x * 256 + threadIdx.x) * 4;
    int4 r = *(const int4*)(rows + i);
    int4 c = *(const int4*)(cols + i);
    g_used[r.x] = 1; g_used[r.y] = 1; g_used[r.z] = 1; g_used[r.w] = 1;
    g_used[NUSERS + c.x] = 1; g_used[NUSERS + c.y] = 1;
    g_used[NUSERS + c.z] = 1; g_used[NUSERS + c.w] = 1;
}
__global__ __launch_bounds__(256) void build_list() {
    const int e = blockIdx.x * 256 + threadIdx.x;
    if (e < NEMB && g_used[e]) {
        int p = atomicAdd(&g_cnt, 1);
        g_list[p] = e;
    }
}

// ---------------------------------------------------------------------------
// fp32 -> bf16 embedding conversion, USED rows only.
// ---------------------------------------------------------------------------
__global__ __launch_bounds__(256) void conv_emb(
    const float* __restrict__ user_inter, const float* __restrict__ item_inter,
    __nv_bfloat16* __restrict__ Eb)
{
    const int t = threadIdx.x;
    if (t >= 240) return;
    const int r0 = blockIdx.x * 2;
    const uchar2 u = *(const uchar2*)(g_used + r0);

    const float* s0 = (r0 < NUSERS) ? user_inter + (size_t)r0 * DIMC
                                    : item_inter + (size_t)(r0 - NUSERS) * DIMC;
    const int r1 = r0 + 1;
    const float* s1 = (r1 < NUSERS) ? user_inter + (size_t)r1 * DIMC
                                    : item_inter + (size_t)(r1 - NUSERS) * DIMC;
    float4 v0, v1;
    if (u.x) v0 = *(const float4*)(s0 + t * 4);
    if (u.y) v1 = *(const float4*)(s1 + t * 4);
    if (u.x) {
        __nv_bfloat16* d = Eb + (size_t)r0 * DIMC + t * 4;
        *(__nv_bfloat162*)(d)     = __nv_bfloat162(__float2bfloat16(v0.x), __float2bfloat16(v0.y));
        *(__nv_bfloat162*)(d + 2) = __nv_bfloat162(__float2bfloat16(v0.z), __float2bfloat16(v0.w));
    }
    if (u.y) {
        __nv_bfloat16* d = Eb + (size_t)r1 * DIMC + t * 4;
        *(__nv_bfloat162*)(d)     = __nv_bfloat162(__float2bfloat16(v1.x), __float2bfloat16(v1.y));
        *(__nv_bfloat162*)(d + 2) = __nv_bfloat162(__float2bfloat16(v1.z), __float2bfloat16(v1.w));
    }
}

// ---------------------------------------------------------------------------
// Wt | W1 | W2 | W3 fp32 -> bf16
// ---------------------------------------------------------------------------
__device__ __forceinline__ void conv_blk(const float* src, __nv_bfloat16* dst, size_t blk) {
    const size_t i = blk * 1024 + threadIdx.x * 4;
    float4 v = *(const float4*)(src + i);
    *(__nv_bfloat162*)(dst + i)     = __nv_bfloat162(__float2bfloat16(v.x), __float2bfloat16(v.y));
    *(__nv_bfloat162*)(dst + i + 2) = __nv_bfloat162(__float2bfloat16(v.z), __float2bfloat16(v.w));
}
__global__ __launch_bounds__(256) void conv_w(
    const float* __restrict__ Wt, const float* __restrict__ W1,
    const float* __restrict__ W2, const float* __restrict__ W3,
    __nv_bfloat16* __restrict__ Wtb, __nv_bfloat16* __restrict__ W1b,
    __nv_bfloat16* __restrict__ W2b, __nv_bfloat16* __restrict__ W3b)
{
    const int b = blockIdx.x;
    if      (b < 900)  conv_blk(Wt, Wtb, b);
    else if (b < 1412) conv_blk(W1, W1b, b - 900);
    else if (b < 1540) conv_blk(W2, W2b, b - 1412);
    else               conv_blk(W3, W3b, b - 1540);
}

// ---------------------------------------------------------------------------
// Transfer GEMM over COMPACTED rows.  WNC = N-cols per warp (32 full / 16
// tail).  BN = 4*WNC.  Tail loads only BN B-rows and halves per-warp MMAs.
// ---------------------------------------------------------------------------
template<int WNC>
__global__ __launch_bounds__(256) void gemm_tr(
    const __nv_bfloat16* __restrict__ Eb, const __nv_bfloat16* __restrict__ Bw,
    const float* __restrict__ bias, __nv_bfloat16* __restrict__ T, int bn0)
{
    constexpr int BN  = 4 * WNC;        // 128 or 64
    constexpr int NTI = WNC / 8;        // 4 or 2 n-tiles per warp
    const int cnt = g_cnt;
    const int bm = blockIdx.y * 128;
    if (bm >= cnt) return;
    const int bn = bn0 + blockIdx.x * BN;

    extern __shared__ char smem[];
    const uint32_t base = smem_u32(smem);
    const int t = threadIdx.x;
    const int wid = t >> 5, lane = t & 31;
    const int wm = wid >> 2, wn = wid & 3;
    const int g = lane >> 2, q = lane & 3;

    constexpr int TILE = 16384;
    constexpr int SB   = TILE + BN * 128;

    float* biass = (float*)(smem);
    int*   idxs  = (int*)(smem + 1024);
    const uint32_t tiles = (base + 3072 + 1023) & ~1023u;

    for (int j = t; j < 128; j += 256) {
        int gn = bn + j;
        biass[j] = (j < BN && gn < DIMC) ? bias[gn] : 0.f;
        idxs[j]  = (bm + j < cnt) ? __ldg(g_list + bm + j) : 0;
    }

    const int seg = t & 7;
    const int rb  = t >> 3;

    int aidx[4]; uint32_t aok[4];
#pragma unroll
    for (int rr = 0; rr < 4; rr++) {
        int gr = bm + rb + rr * 32;
        aok[rr]  = (gr < cnt) ? 16u : 0u;
        aidx[rr] = (gr < cnt) ? __ldg(g_list + gr) : 0;
    }

    auto load_chunk = [&](int c, int s) {
        const uint32_t at = tiles + s * SB;
        const uint32_t bt_ = at + TILE;
#pragma unroll
        for (int rr = 0; rr < 4; rr++) {
            int row = rb + rr * 32;
            const __nv_bfloat16* src = Eb + (size_t)aidx[rr] * DIMC + c * 64 + seg * 8;
            cp16(at + SWZ128(row * 128 + seg * 16), src, aok[rr]);
        }
#pragma unroll
        for (int rr = 0; rr < BN / 32; rr++) {
            int row = rb + rr * 32;
            int gn  = bn + row;
            int ok  = gn < DIMC;
            const __nv_bfloat16* src = Bw + (size_t)(ok ? gn : 0) * DIMC + c * 64 + seg * 8;
            cp16(bt_ + SWZ128(row * 128 + seg * 16), src, ok ? 16u : 0u);
        }
        asm volatile("cp.async.commit_group;" ::: "memory");
    };

    float acc[4][NTI][4];
#pragma unroll
    for (int i = 0; i < 4; i++)
#pragma unroll
        for (int j = 0; j < NTI; j++)
#pragma unroll
            for (int v = 0; v < 4; v++) acc[i][j][v] = 0.f;

    const int arow = lane & 15;
    const int aoff = (lane >> 4) * 16;
    const int axor = (arow & 7) << 4;
    const int bm8  = lane >> 3;
    const int brow = ((bm8 >> 1) << 3) + (lane & 7);
    const int boff = (bm8 & 1) * 16;
    const int bxor = (lane & 7) << 4;
    uint32_t off_a[4], off_b[4];
#pragma unroll
    for (int ks = 0; ks < 4; ks++) {
        off_a[ks] = (uint32_t)((wm * 64 + arow) * 128 + ((ks * 32 + aoff) ^ axor));
        off_b[ks] = (uint32_t)((wn * WNC + brow) * 128 + ((ks * 32 + boff) ^ bxor)) + TILE;
    }

    const int NKc = DIMC >> 6;
    load_chunk(0, 0);
    load_chunk(1, 1);

    for (int i = 0; i < NKc; i++) {
        const int s = i - (i / 3) * 3;
        if (i + 1 < NKc) asm volatile("cp.async.wait_group 1;" ::: "memory");
        else             asm volatile("cp.async.wait_group 0;" ::: "memory");
        __syncthreads();
        if (i + 2 < NKc) {
            int s2 = i + 2; s2 -= (s2 / 3) * 3;
            load_chunk(i + 2, s2);
        }

        const uint32_t st = tiles + s * SB;
#pragma unroll
        for (int ks = 0; ks < 4; ks++) {
            uint32_t af[4][4], bf[NTI][2];
            const uint32_t ab = st + off_a[ks];
            const uint32_t bb = st + off_b[ks];
#pragma unroll
            for (int mt = 0; mt < 4; mt++)
                ldsm4(af[mt], ab + mt * 2048);
#pragma unroll
            for (int np = 0; np < NTI / 2; np++) {
                uint32_t r[4];
                ldsm4(r, bb + np * 2048);
                bf[2 * np][0] = r[0]; bf[2 * np][1] = r[1];
                bf[2 * np + 1][0] = r[2]; bf[2 * np + 1][1] = r[3];
            }
#pragma unroll
            for (int mt = 0; mt < 4; mt++)
#pragma unroll
                for (int nt = 0; nt < NTI; nt++)
                    mma16(acc[mt][nt], af[mt], bf[nt]);
        }
    }
    __syncthreads();

#pragma unroll
    for (int mt = 0; mt < 4; mt++) {
        const int er0 = wm * 64 + mt * 16 + g;
#pragma unroll
        for (int nt = 0; nt < NTI; nt++) {
            const int jc = wn * WNC + nt * 8 + 2 * q;
            const int gn = bn + jc;
            if (gn >= DIMC) continue;
            const float bx = biass[jc], by = biass[jc + 1];
            float x0 = acc[mt][nt][0] + bx, x1 = acc[mt][nt][1] + by;
            float x2 = acc[mt][nt][2] + bx, x3 = acc[mt][nt][3] + by;
            if (bm + er0 < cnt)
                *(__nv_bfloat162*)(T + (size_t)idxs[er0] * DIMC + gn) =
                    __nv_bfloat162(__float2bfloat16(x0), __float2bfloat16(x1));
            if (bm + er0 + 8 < cnt)
                *(__nv_bfloat162*)(T + (size_t)idxs[er0 + 8] * DIMC + gn) =
                    __nv_bfloat162(__float2bfloat16(x2), __float2bfloat16(x3));
        }
    }
}

// ---------------------------------------------------------------------------
// bf16 mma.sync NT GEMM: BM=BN=128, 3-stage cp.async, ldmatrix hoisted.
// FINAL fuses out[b] = tanh(row).Wr + br + 3.5 (N==128).
// ---------------------------------------------------------------------------
template<bool TANH, bool OUT_BF16, bool FINAL>
__global__ __launch_bounds__(256) void gemm_bf(
    const __nv_bfloat16* __restrict__ A, const __nv_bfloat16* __restrict__ Bw,
    const float* __restrict__ bias, void* __restrict__ Cv,
    const float* __restrict__ Wr, const float* __restrict__ brp,
    int M, int N, int K)
{
    extern __shared__ char smem[];
    const uint32_t base = smem_u32(smem);
    const int t = threadIdx.x;
    const int wid = t >> 5, lane = t & 31;
    const int wm = wid >> 2, wn = wid & 3;
    const int g = lane >> 2, q = lane & 3;

    constexpr int TILE = 16384;
    constexpr int SB   = 2 * TILE;
    const int bm = blockIdx.y * 128;
    const int bn = blockIdx.x * 128;

    float* biass = (float*)(smem);
    float* wrs   = (float*)(smem + 512);
    float* part  = (float*)(smem + 1024);
    const uint32_t tiles = (base + 3072 + 1023) & ~1023u;

    for (int j = t; j < 128; j += 256) {
        int gn = bn + j;
        biass[j] = (gn < N) ? bias[gn] : 0.f;
        if (FINAL) wrs[j] = Wr[j];
    }

    const int seg = t & 7;
    const int rb  = t >> 3;

    auto load_chunk = [&](int c, int s) {
        const uint32_t at = tiles + s * SB;
        const uint32_t bt_ = at + TILE;
#pragma unroll
        for (int rr = 0; rr < 4; rr++) {
            int row = rb + rr * 32;
            int gr  = bm + row;
            int ok  = gr < M;
            const __nv_bfloat16* src = A + (size_t)(ok ? gr : 0) * K + c * 64 + seg * 8;
            cp16(at + SWZ128(row * 128 + seg * 16), src, ok ? 16u : 0u);
        }
#pragma unroll
        for (int rr = 0; rr < 4; rr++) {
            int row = rb + rr * 32;
            int gn  = bn + row;
            int ok  = gn < N;
            const __nv_bfloat16* src = Bw + (size_t)(ok ? gn : 0) * K + c * 64 + seg * 8;
            cp16(bt_ + SWZ128(row * 128 + seg * 16), src, ok ? 16u : 0u);
        }
        asm volatile("cp.async.commit_group;" ::: "memory");
    };

    float acc[4][4][4];
#pragma unroll
    for (int i = 0; i < 4; i++)
#pragma unroll
        for (int j = 0; j < 4; j++)
#pragma unroll
            for (int v = 0; v < 4; v++) acc[i][j][v] = 0.f;

    const int arow = lane & 15;
    const int aoff = (lane >> 4) * 16;
    const int axor = (arow & 7) << 4;
    const int bm8  = lane >> 3;
    const int brow = ((bm8 >> 1) << 3) + (lane & 7);
    const int boff = (bm8 & 1) * 16;
    const int bxor = (lane & 7) << 4;
    uint32_t off_a[4], off_b[4];
#pragma unroll
    for (int ks = 0; ks < 4; ks++) {
        off_a[ks] = (uint32_t)((wm * 64 + arow) * 128 + ((ks * 32 + aoff) ^ axor));
        off_b[ks] = (uint32_t)((wn * 32 + brow) * 128 + ((ks * 32 + boff) ^ bxor)) + TILE;
    }

    const int NKc = K >> 6;
    load_chunk(0, 0);
    load_chunk(1, 1);

    for (int i = 0; i < NKc; i++) {
        const int s = i - (i / 3) * 3;
        if (i + 1 < NKc) asm volatile("cp.async.wait_group 1;" ::: "memory");
        else             asm volatile("cp.async.wait_group 0;" ::: "memory");
        __syncthreads();
        if (i + 2 < NKc) {
            int s2 = i + 2; s2 -= (s2 / 3) * 3;
            load_chunk(i + 2, s2);
        }

        const uint32_t st = tiles + s * SB;
#pragma unroll
        for (int ks = 0; ks < 4; ks++) {
            uint32_t af[4][4], bf[4][2];
            const uint32_t ab = st + off_a[ks];
            const uint32_t bb = st + off_b[ks];
#pragma unroll
            for (int mt = 0; mt < 4; mt++)
                ldsm4(af[mt], ab + mt * 2048);
#pragma unroll
            for (int np = 0; np < 2; np++) {
                uint32_t r[4];
                ldsm4(r, bb + np * 2048);
                bf[2 * np][0] = r[0]; bf[2 * np][1] = r[1];
                bf[2 * np + 1][0] = r[2]; bf[2 * np + 1][1] = r[3];
            }
#pragma unroll
            for (int mt = 0; mt < 4; mt++)
#pragma unroll
                for (int nt = 0; nt < 4; nt++)
                    mma16(acc[mt][nt], af[mt], bf[nt]);
        }
    }
    __syncthreads();

    if (FINAL) {
#pragma unroll
        for (int mt = 0; mt < 4; mt++) {
            float p0 = 0.f, p1 = 0.f;
#pragma unroll
            for (int nt = 0; nt < 4; nt++) {
                const int jc = wn * 32 + nt * 8 + 2 * q;
                const float bx = biass[jc], by = biass[jc + 1];
                const float wx = wrs[jc],  wy = wrs[jc + 1];
                p0 += tanhf(acc[mt][nt][0] + bx) * wx + tanhf(acc[mt][nt][1] + by) * wy;
                p1 += tanhf(acc[mt][nt][2] + bx) * wx + tanhf(acc[mt][nt][3] + by) * wy;
            }
            p0 += __shfl_xor_sync(0xFFFFFFFFu, p0, 1);
            p0 += __shfl_xor_sync(0xFFFFFFFFu, p0, 2);
            p1 += __shfl_xor_sync(0xFFFFFFFFu, p1, 1);
            p1 += __shfl_xor_sync(0xFFFFFFFFu, p1, 2);
            if (q == 0) {
                part[(wm * 64 + mt * 16 + g) * 4 + wn]     = p0;
                part[(wm * 64 + mt * 16 + g + 8) * 4 + wn] = p1;
            }
        }
        __syncthreads();
        if (t < 128) {
            float s = part[t * 4] + part[t * 4 + 1] + part[t * 4 + 2] + part[t * 4 + 3];
            if (bm + t < M) ((float*)Cv)[bm + t] = s + brp[0] + 3.5f;
        }
        return;
    }

#pragma unroll
    for (int mt = 0; mt < 4; mt++) {
        const int r0 = bm + wm * 64 + mt * 16 + g;
#pragma unroll
        for (int nt = 0; nt < 4; nt++) {
            const int jc = wn * 32 + nt * 8 + 2 * q;
            const int gn = bn + jc;
            if (gn >= N) continue;
            const float bx = biass[jc], by = biass[jc + 1];
            float x0 = acc[mt][nt][0] + bx, x1 = acc[mt][nt][1] + by;
            float x2 = acc[mt][nt][2] + bx, x3 = acc[mt][nt][3] + by;
            if (TANH) { x0 = tanhf(x0); x1 = tanhf(x1); x2 = tanhf(x2); x3 = tanhf(x3); }
            if (OUT_BF16) {
                __nv_bfloat16* C = (__nv_bfloat16*)Cv;
                if (r0 < M)
                    *(__nv_bfloat162*)(C + (size_t)r0 * N + gn) =
                        __nv_bfloat162(__float2bfloat16(x0), __float2bfloat16(x1));
                if (r0 + 8 < M)
                    *(__nv_bfloat162*)(C + (size_t)(r0 + 8) * N + gn) =
                        __nv_bfloat162(__float2bfloat16(x2), __float2bfloat16(x3));
            } else {
                float* C = (float*)Cv;
                if (r0 < M)     *(float2*)(C + (size_t)r0 * N + gn)       = make_float2(x0, x1);
                if (r0 + 8 < M) *(float2*)(C + (size_t)(r0 + 8) * N + gn) = make_float2(x2, x3);
            }
        }
    }
}

// ---------------------------------------------------------------------------
// Gather + elementwise product + concat into F0[B, 1024] (bf16).
// ---------------------------------------------------------------------------
__global__ __launch_bounds__(256) void build_factor(
    const int* __restrict__ rows, const int* __restrict__ cols,
    const float* __restrict__ uix, const float* __restrict__ iix,
    const __nv_bfloat16* __restrict__ T, __nv_bfloat16* __restrict__ F0)
{
    const int b0 = blockIdx.x * BF_E;
    const int t  = threadIdx.x;
    const int f  = t * 4;

    int rr[BF_E], cc[BF_E];
    {
        int4 ra = *(const int4*)(rows + b0);
        int4 rb_ = *(const int4*)(rows + b0 + 4);
        int4 ca = *(const int4*)(cols + b0);
        int4 cb = *(const int4*)(cols + b0 + 4);
        rr[0] = ra.x; rr[1] = ra.y; rr[2] = ra.z; rr[3] = ra.w;
        rr[4] = rb_.x; rr[5] = rb_.y; rr[6] = rb_.z; rr[7] = rb_.w;
        cc[0] = ca.x; cc[1] = ca.y; cc[2] = ca.z; cc[3] = ca.w;
        cc[4] = cb.x; cc[5] = cb.y; cc[6] = cb.z; cc[7] = cb.w;
    }

    if (f < 32) {
        float4 v[BF_E];
#pragma unroll
        for (int e = 0; e < BF_E; e++)
            v[e] = *(const float4*)(uix + (size_t)rr[e] * DIMS + f);
#pragma unroll
        for (int e = 0; e < BF_E; e++) {
            __nv_bfloat16* o = F0 + (size_t)(b0 + e) * 1024 + f;
            *(__nv_bfloat162*)(o)     = __nv_bfloat162(__float2bfloat16(v[e].x), __float2bfloat16(v[e].y));
            *(__nv_bfloat162*)(o + 2) = __nv_bfloat162(__float2bfloat16(v[e].z), __float2bfloat16(v[e].w));
        }
    } else if (f < 64) {
        float4 v[BF_E];
#pragma unroll
        for (int e = 0; e < BF_E; e++)
            v[e] = *(const float4*)(iix + (size_t)cc[e] * DIMS + (f - 32));
#pragma unroll
        for (int e = 0; e < BF_E; e++) {
            __nv_bfloat16* o = F0 + (size_t)(b0 + e) * 1024 + f;
            *(__nv_bfloat162*)(o)     = __nv_bfloat162(__float2bfloat16(v[e].x), __float2bfloat16(v[e].y));
            *(__nv_bfloat162*)(o + 2) = __nv_bfloat162(__float2bfloat16(v[e].z), __float2bfloat16(v[e].w));
        }
    } else {
        uint2 av[BF_E], bv[BF_E];
#pragma unroll
        for (int e = 0; e < BF_E; e++)
            av[e] = __ldg((const uint2*)(T + (size_t)rr[e] * DIMC + (f - 64)));
#pragma unroll
        for (int e = 0; e < BF_E; e++)
            bv[e] = __ldg((const uint2*)(T + (size_t)(NUSERS + cc[e]) * DIMC + (f - 64)));
#pragma unroll
        for (int e = 0; e < BF_E; e++) {
            __nv_bfloat162 a0 = *(__nv_bfloat162*)&av[e].x;
            __nv_bfloat162 a1 = *(__nv_bfloat162*)&av[e].y;
            __nv_bfloat162 b0_ = *(__nv_bfloat162*)&bv[e].x;
            __nv_bfloat162 b1_ = *(__nv_bfloat162*)&bv[e].y;
            __nv_bfloat162 p0 = __hmul2(a0, b0_);
            __nv_bfloat162 p1 = __hmul2(a1, b1_);
            uint2 w;
            w.x = *(uint32_t*)&p0;
            w.y = *(uint32_t*)&p1;
            *(uint2*)(F0 + (size_t)(b0 + e) * 1024 + f) = w;
        }
    }
}

// ---------------------------------------------------------------------------
extern "C" void kernel_launch(void* const* d_in, const int* in_sizes, int n_in,
                              void* d_out, int out_size)
{
    const int*   rows       = (const int*)d_in[0];
    const int*   cols       = (const int*)d_in[1];
    const float* user_inter = (const float*)d_in[2];
    const float* item_inter = (const float*)d_in[3];
    const float* uix        = (const float*)d_in[4];
    const float* iix        = (const float*)d_in[5];
    const float* Wt         = (const float*)d_in[6];
    const float* bt         = (const float*)d_in[7];
    const float* W1         = (const float*)d_in[8];
    const float* b1         = (const float*)d_in[9];
    const float* W2         = (const float*)d_in[10];
    const float* b2         = (const float*)d_in[11];
    const float* W3         = (const float*)d_in[12];
    const float* b3         = (const float*)d_in[13];
    const float* Wr         = (const float*)d_in[14];
    const float* br         = (const float*)d_in[15];
    float*       out        = (float*)d_out;

    __nv_bfloat16 *Eb, *Wtb, *T, *W1b, *W2b, *W3b, *F0, *F1, *F2;
    cudaGetSymbolAddress((void**)&Eb,  g_Eb);
    cudaGetSymbolAddress((void**)&Wtb, g_Wtb);
    cudaGetSymbolAddress((void**)&T,   g_T);
    cudaGetSymbolAddress((void**)&W1b, g_W1b);
    cudaGetSymbolAddress((void**)&W2b, g_W2b);
    cudaGetSymbolAddress((void**)&W3b, g_W3b);
    cudaGetSymbolAddress((void**)&F0,  g_F0);
    cudaGetSymbolAddress((void**)&F1,  g_F1);
    cudaGetSymbolAddress((void**)&F2,  g_F2);

    static cudaStream_t s1 = nullptr;
    static cudaEvent_t evFork, evM, evL, evC, evT, evTt, evB;
    if (!s1) {
        cudaStreamCreateWithFlags(&s1, cudaStreamNonBlocking);
        cudaEventCreateWithFlags(&evFork, cudaEventDisableTiming);
        cudaEventCreateWithFlags(&evM,    cudaEventDisableTiming);
        cudaEventCreateWithFlags(&evL,    cudaEventDisableTiming);
        cudaEventCreateWithFlags(&evC,    cudaEventDisableTiming);
        cudaEventCreateWithFlags(&evT,    cudaEventDisableTiming);
        cudaEventCreateWithFlags(&evTt,   cudaEventDisableTiming);
        cudaEventCreateWithFlags(&evB,    cudaEventDisableTiming);
    }

    const int SZ128 = 3072 + 1024 + 3 * 32768;   // main GEMMs (2x16KB tiles)
    const int SZ64  = 3072 + 1024 + 3 * 24576;   // tail (16KB A + 8KB B)
    cudaFuncSetAttribute(gemm_tr<32>, cudaFuncAttributeMaxDynamicSharedMemorySize, SZ128);
    cudaFuncSetAttribute(gemm_tr<16>, cudaFuncAttributeMaxDynamicSharedMemorySize, SZ64);
    cudaFuncSetAttribute(gemm_bf<true, true, false>,  cudaFuncAttributeMaxDynamicSharedMemorySize, SZ128);
    cudaFuncSetAttribute(gemm_bf<true, false, true>,  cudaFuncAttributeMaxDynamicSharedMemorySize, SZ128);

    const dim3 blk(256);
    cudaStream_t s0 = 0;

    // ---- fork ----
    cudaEventRecord(evFork, s0);
    cudaStreamWaitEvent(s1, evFork, 0);

    // s1: weight conversions (independent of embeddings)
    conv_w<<<1572, blk, 0, s1>>>(Wt, W1, W2, W3, Wtb, W1b, W2b, W3b);

    // s0: zero + mark
    zero_aux<<<37, blk, 0, s0>>>();
    mark_used<<<NB / 1024, blk, 0, s0>>>(rows, cols);
    cudaEventRecord(evM, s0);

    // s1: build_list (needs mark)
    cudaStreamWaitEvent(s1, evM, 0);
    build_list<<<(NEMB + 255) / 256, blk, 0, s1>>>();
    cudaEventRecord(evL, s1);

    // s0: embedding conversion (needs mark; overlaps build_list/conv_w)
    conv_emb<<<NEMB / 2, blk, 0, s0>>>(user_inter, item_inter, Eb);
    cudaEventRecord(evC, s0);

    // s0: main transfer GEMM cols [0, 896)
    cudaStreamWaitEvent(s0, evL, 0);
    gemm_tr<32><<<dim3(7, (NEMB + 127) / 128), blk, SZ128, s0>>>(Eb, Wtb, bt, T, 0);
    cudaEventRecord(evT, s0);

    // s1: tail transfer GEMM cols [896, 960) -- overlaps main GEMM
    cudaStreamWaitEvent(s1, evC, 0);
    gemm_tr<16><<<dim3(1, (NEMB + 127) / 128), blk, SZ64, s1>>>(Eb, Wtb, bt, T, 896);
    cudaEventRecord(evTt, s1);

    // ---- two batch-half chains (each needs BOTH transfer parts) ----
    cudaStreamWaitEvent(s0, evTt, 0);
    build_factor<<<NBH / BF_E, blk, 0, s0>>>(rows, cols, uix, iix, T, F0);
    gemm_bf<true, true, false><<<dim3(4, NBH / 128), blk, SZ128, s0>>>(
        F0, W1b, b1, F1, nullptr, nullptr, NBH, 512, 1024);
    gemm_bf<true, true, false><<<dim3(2, NBH / 128), blk, SZ128, s0>>>(
        F1, W2b, b2, F2, nullptr, nullptr, NBH, 256, 512);
    gemm_bf<true, false, true><<<dim3(1, NBH / 128), blk, SZ128, s0>>>(
        F2, W3b, b3, out, Wr, br, NBH, 128, 256);

    cudaStreamWaitEvent(s1, evT, 0);
    build_factor<<<NBH / BF_E, blk, 0, s1>>>(
        rows + NBH, cols + NBH, uix, iix, T, F0 + (size_t)NBH * 1024);
    gemm_bf<true, true, false><<<dim3(4, NBH / 128), blk, SZ128, s1>>>(
        F0 + (size_t)NBH * 1024, W1b, b1, F1 + (size_t)NBH * 512,
        nullptr, nullptr, NBH, 512, 1024);
    gemm_bf<true, true, false><<<dim3(2, NBH / 128), blk, SZ128, s1>>>(
        F1 + (size_t)NBH * 512, W2b, b2, F2 + (size_t)NBH * 256,
        nullptr, nullptr, NBH, 256, 512);
    gemm_bf<true, false, true><<<dim3(1, NBH / 128), blk, SZ128, s1>>>(
        F2 + (size_t)NBH * 256, W3b, b3, out + NBH, Wr, br, NBH, 128, 256);
    cudaEventRecord(evB, s1);

    // ---- join ----
    cudaStreamWaitEvent(s0, evB, 0);
}